// round 1
// baseline (speedup 1.0000x reference)
#include <cuda_runtime.h>

#define BB 8
#define CC 64
#define NP 16384
#define RR 32
#define NV 32768          // 32^3
#define ALPHA 0.1f
#define BNEPS 1e-4f
#define VOXEPS 1e-6f

// ---------------- scratch (device globals; no allocation allowed) ----------
__device__ float g_fT[BB * NP * CC];        // features transposed [b][n][c]   32MB
__device__ float g_tmp[BB * NV * CC];       // voxel sums [b][v][c]; later vT  64MB
__device__ float g_cnt[BB * NV];            // voxel counts
__device__ float g_bufA[BB * CC * NV];      // channel-major grid buffers      64MB
__device__ float g_bufB[BB * CC * NV];      //                                 64MB
__device__ float g_pT[BB * NP * CC];        // point branch [b][n][c]          32MB
__device__ float g_normc[BB * 3 * NP];      // normalized coords in [0,31]
__device__ float g_cmean[BB * 3];
__device__ float g_cmax[BB];
__device__ float g_sum[CC];
__device__ float g_sumsq[CC];

// ---------------- utility kernels ----------------
__global__ void zero_kernel(float* p, size_t n) {
    size_t i = (size_t)blockIdx.x * blockDim.x + threadIdx.x;
    size_t stride = (size_t)gridDim.x * blockDim.x;
    for (; i < n; i += stride) p[i] = 0.0f;
}

__global__ void zero_stats(float* s, float* q) {
    int t = threadIdx.x;
    if (t < CC) { s[t] = 0.0f; q[t] = 0.0f; }
}

__global__ void copy_kernel(const float* __restrict__ src, float* __restrict__ dst, int n) {
    int i = blockIdx.x * blockDim.x + threadIdx.x;
    int stride = gridDim.x * blockDim.x;
    for (; i < n; i += stride) dst[i] = src[i];
}

// ---------------- features transpose [b][c][n] -> [b][n][c] ----------------
__global__ void transpose_feat(const float* __restrict__ feat, float* __restrict__ fT) {
    __shared__ float s[CC][33];
    int b = blockIdx.y;
    int n0 = blockIdx.x * 32;
    int t = threadIdx.x;
    for (int i = t; i < 32 * 64; i += 256) {
        int c = i >> 5, n = i & 31;
        s[c][n] = feat[(b * CC + c) * NP + n0 + n];
    }
    __syncthreads();
    for (int i = t; i < 32 * 64; i += 256) {
        int n = i >> 6, c = i & 63;
        fT[((size_t)b * NP + n0 + n) * CC + c] = s[c][n];
    }
}

// ---------------- coord statistics ----------------
__global__ void coord_mean(const float* __restrict__ coords, float* __restrict__ cmean) {
    int b = blockIdx.x, t = threadIdx.x;
    float s0 = 0, s1 = 0, s2 = 0;
    for (int n = t; n < NP; n += 256) {
        s0 += coords[(b * 3 + 0) * NP + n];
        s1 += coords[(b * 3 + 1) * NP + n];
        s2 += coords[(b * 3 + 2) * NP + n];
    }
    __shared__ float r0[256], r1[256], r2[256];
    r0[t] = s0; r1[t] = s1; r2[t] = s2;
    __syncthreads();
    for (int o = 128; o > 0; o >>= 1) {
        if (t < o) { r0[t] += r0[t + o]; r1[t] += r1[t + o]; r2[t] += r2[t + o]; }
        __syncthreads();
    }
    if (t == 0) {
        cmean[b * 3 + 0] = r0[0] / (float)NP;
        cmean[b * 3 + 1] = r1[0] / (float)NP;
        cmean[b * 3 + 2] = r2[0] / (float)NP;
    }
}

__global__ void coord_max(const float* __restrict__ coords, const float* __restrict__ cmean,
                          float* __restrict__ cmax) {
    int b = blockIdx.x, t = threadIdx.x;
    float mx = cmean[b * 3 + 0], my = cmean[b * 3 + 1], mz = cmean[b * 3 + 2];
    float m = 0.0f;
    for (int n = t; n < NP; n += 256) {
        float dx = coords[(b * 3 + 0) * NP + n] - mx;
        float dy = coords[(b * 3 + 1) * NP + n] - my;
        float dz = coords[(b * 3 + 2) * NP + n] - mz;
        m = fmaxf(m, dx * dx + dy * dy + dz * dz);
    }
    __shared__ float r[256];
    r[t] = m;
    __syncthreads();
    for (int o = 128; o > 0; o >>= 1) {
        if (t < o) r[t] = fmaxf(r[t], r[t + o]);
        __syncthreads();
    }
    if (t == 0) cmax[b] = sqrtf(r[0]);
}

// ---------------- voxelize scatter (4 points per block, 64 threads/point) --
__global__ void scatter(const float* __restrict__ coords, const float* __restrict__ fT,
                        const float* __restrict__ cmean, const float* __restrict__ cmax,
                        float* __restrict__ normc, float* __restrict__ tmp,
                        float* __restrict__ cnt) {
    int t = threadIdx.x;
    int pi = blockIdx.x * 4 + (t >> 6);
    int c = t & 63;
    int b = pi / NP;
    int n = pi - b * NP;

    float inv = 1.0f / (2.0f * cmax[b] + VOXEPS);
    float nx = (coords[(b * 3 + 0) * NP + n] - cmean[b * 3 + 0]) * inv + 0.5f;
    float ny = (coords[(b * 3 + 1) * NP + n] - cmean[b * 3 + 1]) * inv + 0.5f;
    float nz = (coords[(b * 3 + 2) * NP + n] - cmean[b * 3 + 2]) * inv + 0.5f;
    nx = fminf(fmaxf(nx * (float)RR, 0.0f), (float)(RR - 1));
    ny = fminf(fmaxf(ny * (float)RR, 0.0f), (float)(RR - 1));
    nz = fminf(fmaxf(nz * (float)RR, 0.0f), (float)(RR - 1));
    int vx = __float2int_rn(nx), vy = __float2int_rn(ny), vz = __float2int_rn(nz);
    int v = (vx * RR + vy) * RR + vz;

    float f = fT[((size_t)b * NP + n) * CC + c];
    atomicAdd(&tmp[((size_t)b * NV + v) * CC + c], f);
    if (c == 0) atomicAdd(&cnt[b * NV + v], 1.0f);
    if (c < 3) normc[(b * 3 + c) * NP + n] = (c == 0 ? nx : (c == 1 ? ny : nz));
}

// ---------------- finalize: [b][v][c]/count -> [b][c][v] -------------------
__global__ void finalize_vox(const float* __restrict__ tmp, const float* __restrict__ cnt,
                             float* __restrict__ grid) {
    __shared__ float s[CC][33];
    __shared__ float cs[32];
    int b = blockIdx.y;
    int v0 = blockIdx.x * 32;
    int t = threadIdx.x;
    for (int i = t; i < 32 * 64; i += 256) {
        int v = i >> 6, c = i & 63;
        s[c][v] = tmp[((size_t)b * NV + v0 + v) * CC + c];
    }
    if (t < 32) cs[t] = fmaxf(cnt[b * NV + v0 + t], 1.0f);
    __syncthreads();
    for (int i = t; i < 32 * 64; i += 256) {
        int c = i >> 5, v = i & 31;
        grid[((size_t)b * CC + c) * NV + v0 + v] = s[c][v] / cs[v];
    }
}

// ---------------- 3^3 conv (fp32, smem-tiled) ------------------------------
// grid: (16 tiles, 32 z, 8 b), block 256. Each block: 8x8 (y,x) tile, all 64 c_out.
__global__ void conv3d_kernel(const float* __restrict__ in, float* __restrict__ out,
                              const float* __restrict__ w, const float* __restrict__ bias) {
    __shared__ float wsm[27 * 64];
    __shared__ float psm[3 * 10 * 10];
    int b = blockIdx.z, z = blockIdx.y;
    int y0 = (blockIdx.x >> 2) * 8;
    int x0 = (blockIdx.x & 3) * 8;
    int t = threadIdx.x;
    int pos = t >> 2, cog = t & 3;
    int py = pos >> 3, px = pos & 7;

    float a[16];
#pragma unroll
    for (int j = 0; j < 16; j++) a[j] = 0.0f;

    for (int ci = 0; ci < 64; ci++) {
        // weights for this ci: w[(k*64+ci)*64 + co], 27*64 floats
        const float4* w4 = (const float4*)(w + ci * 64);
        float4* ws4 = (float4*)wsm;
        for (int i = t; i < 432; i += 256) {
            int k = i >> 4, j = i & 15;
            ws4[i] = w4[k * 1024 + j];
        }
        // input patch 3x10x10 (zero pad)
        for (int i = t; i < 300; i += 256) {
            int kz = i / 100, r = i - kz * 100;
            int py2 = r / 10, px2 = r - py2 * 10;
            int zz = z - 1 + kz, yy = y0 - 1 + py2, xx = x0 - 1 + px2;
            float v = 0.0f;
            if (zz >= 0 && zz < 32 && yy >= 0 && yy < 32 && xx >= 0 && xx < 32)
                v = in[((size_t)b * CC + ci) * NV + zz * 1024 + yy * 32 + xx];
            psm[i] = v;
        }
        __syncthreads();

        int base = py * 10 + px;
#pragma unroll
        for (int kz = 0; kz < 3; kz++)
#pragma unroll
            for (int ky = 0; ky < 3; ky++)
#pragma unroll
                for (int kx = 0; kx < 3; kx++) {
                    float v = psm[kz * 100 + ky * 10 + base + kx];
                    const float4* wp =
                        (const float4*)&wsm[((kz * 3 + ky) * 3 + kx) * 64 + cog * 16];
                    float4 w0 = wp[0], w1 = wp[1], w2 = wp[2], w3 = wp[3];
                    a[0] += v * w0.x;  a[1] += v * w0.y;  a[2] += v * w0.z;  a[3] += v * w0.w;
                    a[4] += v * w1.x;  a[5] += v * w1.y;  a[6] += v * w1.z;  a[7] += v * w1.w;
                    a[8] += v * w2.x;  a[9] += v * w2.y;  a[10] += v * w2.z; a[11] += v * w2.w;
                    a[12] += v * w3.x; a[13] += v * w3.y; a[14] += v * w3.z; a[15] += v * w3.w;
                }
        __syncthreads();
    }

    int vi = z * 1024 + (y0 + py) * 32 + x0 + px;
#pragma unroll
    for (int j = 0; j < 16; j++) {
        int co = cog * 16 + j;
        out[((size_t)b * CC + co) * NV + vi] = a[j] + bias[co];
    }
}

// ---------------- BN stats over [b][c][v] (per channel) --------------------
__global__ void bnstats(const float* __restrict__ x, float* __restrict__ sum,
                        float* __restrict__ sumsq) {
    int c = blockIdx.x, b = blockIdx.y, t = threadIdx.x;
    const float* p = x + ((size_t)b * CC + c) * NV;
    float s = 0, q = 0;
    for (int i = t; i < NV; i += 256) {
        float v = p[i];
        s += v; q += v * v;
    }
    __shared__ float rs[256], rq[256];
    rs[t] = s; rq[t] = q;
    __syncthreads();
    for (int o = 128; o > 0; o >>= 1) {
        if (t < o) { rs[t] += rs[t + o]; rq[t] += rq[t + o]; }
        __syncthreads();
    }
    if (t == 0) { atomicAdd(&sum[c], rs[0]); atomicAdd(&sumsq[c], rq[0]); }
}

// ---------------- BN apply + LeakyReLU (in-place, [b][c][v]) ---------------
__global__ void bnapply(float* x, const float* __restrict__ gamma, const float* __restrict__ beta,
                        const float* __restrict__ sum, const float* __restrict__ sumsq,
                        float invcnt) {
    size_t i4 = (size_t)blockIdx.x * blockDim.x + threadIdx.x;  // exact grid
    int c = (int)((i4 * 4 / NV) % CC);
    float mean = sum[c] * invcnt;
    float var = sumsq[c] * invcnt - mean * mean;
    float sc = gamma[c] * rsqrtf(var + BNEPS);
    float sh = beta[c] - mean * sc;
    float4* p = (float4*)x;
    float4 v = p[i4];
    float u;
    u = v.x * sc + sh; v.x = u >= 0 ? u : ALPHA * u;
    u = v.y * sc + sh; v.y = u >= 0 ? u : ALPHA * u;
    u = v.z * sc + sh; v.z = u >= 0 ? u : ALPHA * u;
    u = v.w * sc + sh; v.w = u >= 0 ? u : ALPHA * u;
    p[i4] = v;
}

// ---------------- BN apply + LeakyReLU + transpose to [b][v][c] ------------
__global__ void bnapply_T(const float* __restrict__ x, const float* __restrict__ gamma,
                          const float* __restrict__ beta, const float* __restrict__ sum,
                          const float* __restrict__ sumsq, float invcnt,
                          float* __restrict__ vT) {
    __shared__ float s[CC][33];
    int b = blockIdx.y;
    int v0 = blockIdx.x * 32;
    int t = threadIdx.x;
    for (int i = t; i < 32 * 64; i += 256) {
        int c = i >> 5, v = i & 31;
        float mean = sum[c] * invcnt;
        float var = sumsq[c] * invcnt - mean * mean;
        float sc = gamma[c] * rsqrtf(var + BNEPS);
        float sh = beta[c] - mean * sc;
        float u = x[((size_t)b * CC + c) * NV + v0 + v] * sc + sh;
        s[c][v] = u >= 0 ? u : ALPHA * u;
    }
    __syncthreads();
    for (int i = t; i < 32 * 64; i += 256) {
        int v = i >> 6, c = i & 63;
        vT[((size_t)b * NV + v0 + v) * CC + c] = s[c][v];
    }
}

// ---------------- point branch GEMM: p[b][n][d] = feat[b][:,n] . W ---------
__global__ void pgemm(const float* __restrict__ feat, const float* __restrict__ w,
                      const float* __restrict__ bias, float* __restrict__ pT) {
    __shared__ float wsm[64 * 64];
    int b = blockIdx.y;
    int n = blockIdx.x * 256 + threadIdx.x;
    int t = threadIdx.x;
    for (int i = t; i < 4096; i += 256) wsm[i] = w[i];
    __syncthreads();
    float a[64];
#pragma unroll
    for (int j = 0; j < 64; j++) a[j] = 0.0f;
    for (int c = 0; c < 64; c++) {
        float f = feat[((size_t)b * CC + c) * NP + n];
        const float4* wr = (const float4*)&wsm[c * 64];
#pragma unroll
        for (int j = 0; j < 16; j++) {
            float4 w4 = wr[j];
            a[4 * j + 0] += f * w4.x;
            a[4 * j + 1] += f * w4.y;
            a[4 * j + 2] += f * w4.z;
            a[4 * j + 3] += f * w4.w;
        }
    }
    float4* o4 = (float4*)&pT[((size_t)b * NP + n) * CC];
#pragma unroll
    for (int j = 0; j < 16; j++) {
        float4 v;
        v.x = a[4 * j + 0] + bias[4 * j + 0];
        v.y = a[4 * j + 1] + bias[4 * j + 1];
        v.z = a[4 * j + 2] + bias[4 * j + 2];
        v.w = a[4 * j + 3] + bias[4 * j + 3];
        o4[j] = v;
    }
}

// ---------------- point-branch BN stats over [b][n][c] ---------------------
__global__ void pstats(const float* __restrict__ pT, float* __restrict__ sum,
                       float* __restrict__ sumsq) {
    int b = blockIdx.y, t = threadIdx.x;
    int c = t & 63, nl = t >> 6;
    int n0 = blockIdx.x * 256;
    float s = 0, q = 0;
    for (int n = n0 + nl; n < n0 + 256; n += 4) {
        float v = pT[((size_t)b * NP + n) * CC + c];
        s += v; q += v * v;
    }
    __shared__ float rs[256], rq[256];
    rs[t] = s; rq[t] = q;
    __syncthreads();
    if (t < 64) {
        s = rs[t] + rs[t + 64] + rs[t + 128] + rs[t + 192];
        q = rq[t] + rq[t + 64] + rq[t + 128] + rq[t + 192];
        atomicAdd(&sum[c], s);
        atomicAdd(&sumsq[c], q);
    }
}

// ---------------- final: devoxelize + BN(p)+lrelu + add, write [b][c][n] ---
__global__ void final_k(const float* __restrict__ vT, const float* __restrict__ pT,
                        const float* __restrict__ normc, const float* __restrict__ gamma,
                        const float* __restrict__ beta, const float* __restrict__ sum,
                        const float* __restrict__ sumsq, float* __restrict__ out) {
    __shared__ float res[64][65];
    __shared__ int cidx[64][8];
    __shared__ float cw[64][8];
    int b = blockIdx.y;
    int n0 = blockIdx.x * 64;
    int t = threadIdx.x;

    if (t < 64) {
        int n = n0 + t;
        float xs = normc[(b * 3 + 0) * NP + n];
        float ys = normc[(b * 3 + 1) * NP + n];
        float zs = normc[(b * 3 + 2) * NP + n];
        float x0f = floorf(xs), y0f = floorf(ys), z0f = floorf(zs);
        float fx = xs - x0f, fy = ys - y0f, fz = zs - z0f;
        int x0 = (int)x0f, y0 = (int)y0f, z0 = (int)z0f;
        int x1 = min(x0 + 1, 31), y1 = min(y0 + 1, 31), z1 = min(z0 + 1, 31);
#pragma unroll
        for (int k = 0; k < 8; k++) {
            int dx = (k >> 2) & 1, dy = (k >> 1) & 1, dz = k & 1;
            float wt = (dx ? fx : 1.0f - fx) * (dy ? fy : 1.0f - fy) * (dz ? fz : 1.0f - fz);
            int idx = ((dx ? x1 : x0) * 32 + (dy ? y1 : y0)) * 32 + (dz ? z1 : z0);
            cidx[t][k] = idx;
            cw[t][k] = wt;
        }
    }
    __syncthreads();

    int c = t & 63, ty = t >> 6;
    float invc = 1.0f / (float)(BB * NP);
    float mean = sum[c] * invc;
    float var = sumsq[c] * invc - mean * mean;
    float sc = gamma[c] * rsqrtf(var + BNEPS);
    float sh = beta[c] - mean * sc;

    for (int j = ty; j < 64; j += 4) {
        float acc = 0.0f;
#pragma unroll
        for (int k = 0; k < 8; k++)
            acc += cw[j][k] * vT[((size_t)b * NV + cidx[j][k]) * CC + c];
        float pv = pT[((size_t)b * NP + n0 + j) * CC + c] * sc + sh;
        pv = pv >= 0 ? pv : ALPHA * pv;
        res[c][j] = acc + pv;
    }
    __syncthreads();

    for (int i = t; i < 4096; i += 256) {
        int c2 = i >> 6, j = i & 63;
        out[((size_t)b * CC + c2) * NP + n0 + j] = res[c2][j];
    }
}

// ---------------- launcher ----------------
extern "C" void kernel_launch(void* const* d_in, const int* in_sizes, int n_in,
                              void* d_out, int out_size) {
    const float* feat   = (const float*)d_in[0];
    const float* coords = (const float*)d_in[1];
    const float* c1w    = (const float*)d_in[2];
    const float* c1b    = (const float*)d_in[3];
    const float* g1     = (const float*)d_in[4];
    const float* b1     = (const float*)d_in[5];
    const float* c2w    = (const float*)d_in[6];
    const float* c2b    = (const float*)d_in[7];
    const float* g2     = (const float*)d_in[8];
    const float* b2     = (const float*)d_in[9];
    const float* pw     = (const float*)d_in[10];
    const float* pb     = (const float*)d_in[11];
    const float* pg     = (const float*)d_in[12];
    const float* pbeta  = (const float*)d_in[13];
    float* out = (float*)d_out;

    float *fT, *tmp, *cnt, *bufA, *bufB, *pT, *normc, *cmean, *cmax, *sum, *sumsq;
    cudaGetSymbolAddress((void**)&fT, g_fT);
    cudaGetSymbolAddress((void**)&tmp, g_tmp);
    cudaGetSymbolAddress((void**)&cnt, g_cnt);
    cudaGetSymbolAddress((void**)&bufA, g_bufA);
    cudaGetSymbolAddress((void**)&bufB, g_bufB);
    cudaGetSymbolAddress((void**)&pT, g_pT);
    cudaGetSymbolAddress((void**)&normc, g_normc);
    cudaGetSymbolAddress((void**)&cmean, g_cmean);
    cudaGetSymbolAddress((void**)&cmax, g_cmax);
    cudaGetSymbolAddress((void**)&sum, g_sum);
    cudaGetSymbolAddress((void**)&sumsq, g_sumsq);

    // voxelize
    zero_kernel<<<8192, 256>>>(tmp, (size_t)BB * NV * CC);
    zero_kernel<<<256, 256>>>(cnt, (size_t)BB * NV);
    transpose_feat<<<dim3(NP / 32, BB), 256>>>(feat, fT);
    coord_mean<<<BB, 256>>>(coords, cmean);
    coord_max<<<BB, 256>>>(coords, cmean, cmax);
    scatter<<<BB * NP / 4, 256>>>(coords, fT, cmean, cmax, normc, tmp, cnt);
    finalize_vox<<<dim3(NV / 32, BB), 256>>>(tmp, cnt, bufA);

    // conv1 + BN + lrelu
    conv3d_kernel<<<dim3(16, 32, BB), 256>>>(bufA, bufB, c1w, c1b);
    zero_stats<<<1, 64>>>(sum, sumsq);
    bnstats<<<dim3(CC, BB), 256>>>(bufB, sum, sumsq);
    bnapply<<<(BB * CC * NV / 4) / 256, 256>>>(bufB, g1, b1, sum, sumsq, 1.0f / (float)(BB * NV));

    // conv2 + BN + lrelu + transpose to [b][v][c] (reuse tmp as vT)
    conv3d_kernel<<<dim3(16, 32, BB), 256>>>(bufB, bufA, c2w, c2b);
    zero_stats<<<1, 64>>>(sum, sumsq);
    bnstats<<<dim3(CC, BB), 256>>>(bufA, sum, sumsq);
    bnapply_T<<<dim3(NV / 32, BB), 256>>>(bufA, g2, b2, sum, sumsq, 1.0f / (float)(BB * NV), tmp);

    // point branch
    pgemm<<<dim3(NP / 256, BB), 256>>>(feat, pw, pb, pT);
    zero_stats<<<1, 64>>>(sum, sumsq);
    pstats<<<dim3(NP / 256, BB), 256>>>(pT, sum, sumsq);

    // devoxelize + point BN + add
    final_k<<<dim3(NP / 64, BB), 256>>>(tmp, pT, normc, pg, pbeta, sum, sumsq, out);

    // coords passthrough (second tuple output), if the harness expects it
    int main_sz = BB * CC * NP;
    int coord_sz = BB * 3 * NP;
    if (out_size >= main_sz + coord_sz)
        copy_kernel<<<coord_sz / 256, 256>>>(coords, out + main_sz, coord_sz);
}

// round 2
// speedup vs baseline: 4.1338x; 4.1338x over previous
#include <cuda_runtime.h>

#define BB 8
#define CC 64
#define NP 16384
#define RR 32
#define NV 32768          // 32^3
#define ALPHA 0.1f
#define BNEPS 1e-4f
#define VOXEPS 1e-6f

// ---------------- scratch (device globals; no allocation allowed) ----------
__device__ float g_fT[BB * NP * CC];        // features transposed [b][n][c]
__device__ float g_tmp[BB * NV * CC];       // voxel sums [b][v][c]; later vT
__device__ float g_cnt[BB * NV];            // voxel counts
__device__ float g_bufA[BB * CC * NV];      // channel-major grid buffers
__device__ float g_bufB[BB * CC * NV];
__device__ float g_pT[BB * NP * CC];        // point branch [b][n][c]
__device__ float g_normc[BB * 3 * NP];      // normalized coords in [0,31]
__device__ float g_cmean[BB * 3];
__device__ float g_cmax[BB];
__device__ float g_sum[CC];
__device__ float g_sumsq[CC];

// ---------------- utility kernels ----------------
__global__ void zero_kernel(float* p, size_t n) {
    size_t i = (size_t)blockIdx.x * blockDim.x + threadIdx.x;
    size_t stride = (size_t)gridDim.x * blockDim.x;
    for (; i < n; i += stride) p[i] = 0.0f;
}

__global__ void zero_stats(float* s, float* q) {
    int t = threadIdx.x;
    if (t < CC) { s[t] = 0.0f; q[t] = 0.0f; }
}

__global__ void copy_kernel(const float* __restrict__ src, float* __restrict__ dst, int n) {
    int i = blockIdx.x * blockDim.x + threadIdx.x;
    int stride = gridDim.x * blockDim.x;
    for (; i < n; i += stride) dst[i] = src[i];
}

// ---------------- features transpose [b][c][n] -> [b][n][c] ----------------
__global__ void transpose_feat(const float* __restrict__ feat, float* __restrict__ fT) {
    __shared__ float s[CC][33];
    int b = blockIdx.y;
    int n0 = blockIdx.x * 32;
    int t = threadIdx.x;
    for (int i = t; i < 32 * 64; i += 256) {
        int c = i >> 5, n = i & 31;
        s[c][n] = feat[(b * CC + c) * NP + n0 + n];
    }
    __syncthreads();
    for (int i = t; i < 32 * 64; i += 256) {
        int n = i >> 6, c = i & 63;
        fT[((size_t)b * NP + n0 + n) * CC + c] = s[c][n];
    }
}

// ---------------- coord statistics ----------------
__global__ void coord_mean(const float* __restrict__ coords, float* __restrict__ cmean) {
    int b = blockIdx.x, t = threadIdx.x;
    float s0 = 0, s1 = 0, s2 = 0;
    for (int n = t; n < NP; n += 256) {
        s0 += coords[(b * 3 + 0) * NP + n];
        s1 += coords[(b * 3 + 1) * NP + n];
        s2 += coords[(b * 3 + 2) * NP + n];
    }
    __shared__ float r0[256], r1[256], r2[256];
    r0[t] = s0; r1[t] = s1; r2[t] = s2;
    __syncthreads();
    for (int o = 128; o > 0; o >>= 1) {
        if (t < o) { r0[t] += r0[t + o]; r1[t] += r1[t + o]; r2[t] += r2[t + o]; }
        __syncthreads();
    }
    if (t == 0) {
        cmean[b * 3 + 0] = r0[0] / (float)NP;
        cmean[b * 3 + 1] = r1[0] / (float)NP;
        cmean[b * 3 + 2] = r2[0] / (float)NP;
    }
}

__global__ void coord_max(const float* __restrict__ coords, const float* __restrict__ cmean,
                          float* __restrict__ cmax) {
    int b = blockIdx.x, t = threadIdx.x;
    float mx = cmean[b * 3 + 0], my = cmean[b * 3 + 1], mz = cmean[b * 3 + 2];
    float m = 0.0f;
    for (int n = t; n < NP; n += 256) {
        float dx = coords[(b * 3 + 0) * NP + n] - mx;
        float dy = coords[(b * 3 + 1) * NP + n] - my;
        float dz = coords[(b * 3 + 2) * NP + n] - mz;
        m = fmaxf(m, dx * dx + dy * dy + dz * dz);
    }
    __shared__ float r[256];
    r[t] = m;
    __syncthreads();
    for (int o = 128; o > 0; o >>= 1) {
        if (t < o) r[t] = fmaxf(r[t], r[t + o]);
        __syncthreads();
    }
    if (t == 0) cmax[b] = sqrtf(r[0]);
}

// ---------------- voxelize scatter (4 points per block, 64 threads/point) --
__global__ void scatter(const float* __restrict__ coords, const float* __restrict__ fT,
                        const float* __restrict__ cmean, const float* __restrict__ cmax,
                        float* __restrict__ normc, float* __restrict__ tmp,
                        float* __restrict__ cnt) {
    int t = threadIdx.x;
    int pi = blockIdx.x * 4 + (t >> 6);
    int c = t & 63;
    int b = pi / NP;
    int n = pi - b * NP;

    float inv = 1.0f / (2.0f * cmax[b] + VOXEPS);
    float nx = (coords[(b * 3 + 0) * NP + n] - cmean[b * 3 + 0]) * inv + 0.5f;
    float ny = (coords[(b * 3 + 1) * NP + n] - cmean[b * 3 + 1]) * inv + 0.5f;
    float nz = (coords[(b * 3 + 2) * NP + n] - cmean[b * 3 + 2]) * inv + 0.5f;
    nx = fminf(fmaxf(nx * (float)RR, 0.0f), (float)(RR - 1));
    ny = fminf(fmaxf(ny * (float)RR, 0.0f), (float)(RR - 1));
    nz = fminf(fmaxf(nz * (float)RR, 0.0f), (float)(RR - 1));
    int vx = __float2int_rn(nx), vy = __float2int_rn(ny), vz = __float2int_rn(nz);
    int v = (vx * RR + vy) * RR + vz;

    float f = fT[((size_t)b * NP + n) * CC + c];
    atomicAdd(&tmp[((size_t)b * NV + v) * CC + c], f);
    if (c == 0) atomicAdd(&cnt[b * NV + v], 1.0f);
    if (c < 3) normc[(b * 3 + c) * NP + n] = (c == 0 ? nx : (c == 1 ? ny : nz));
}

// ---------------- finalize: [b][v][c]/count -> [b][c][v] -------------------
__global__ void finalize_vox(const float* __restrict__ tmp, const float* __restrict__ cnt,
                             float* __restrict__ grid) {
    __shared__ float s[CC][33];
    __shared__ float cs[32];
    int b = blockIdx.y;
    int v0 = blockIdx.x * 32;
    int t = threadIdx.x;
    for (int i = t; i < 32 * 64; i += 256) {
        int v = i >> 6, c = i & 63;
        s[c][v] = tmp[((size_t)b * NV + v0 + v) * CC + c];
    }
    if (t < 32) cs[t] = fmaxf(cnt[b * NV + v0 + t], 1.0f);
    __syncthreads();
    for (int i = t; i < 32 * 64; i += 256) {
        int c = i >> 5, v = i & 31;
        grid[((size_t)b * CC + c) * NV + v0 + v] = s[c][v] / cs[v];
    }
}

// ---------------- 3^3 conv v2: FFMA2 packed fp32, conflict-free smem -------
// Block: 64 c_out x (4y x 32x) spatial, fixed (z, b). 256 threads.
// Thread: 8 c_out (cog = t>>5, co = cog*8..cog*8+7) x 4 spatial (sy=0..3, sx=t&31).
// ci processed in chunks of 4. Weights broadcast per-warp; patch pre-duplicated
// as float2{v,v} so the B operand of fma.rn.f32x2 is a single LDS.64.
__global__ __launch_bounds__(256) void conv3d_v2(const float* __restrict__ in,
                                                 float* __restrict__ out,
                                                 const float* __restrict__ w,
                                                 const float* __restrict__ bias) {
    __shared__ __align__(16) float wsm[4 * 27 * 64];    // 27648 B
    __shared__ __align__(16) float2 psm[4 * 3 * 6 * 36]; // 20736 B
    int b = blockIdx.z, z = blockIdx.y, y0 = blockIdx.x * 4;
    int t = threadIdx.x;
    int sx = t & 31, cog = t >> 5;

    unsigned long long acc[16];   // [copair 0..3][sy 0..3]
#pragma unroll
    for (int i = 0; i < 16; i++) acc[i] = 0ULL;

    const size_t inb = (size_t)b * CC * NV;
    unsigned wsm_s = (unsigned)__cvta_generic_to_shared(wsm);
    unsigned psm_s = (unsigned)__cvta_generic_to_shared(psm);

    for (int cb = 0; cb < 16; cb++) {
        // --- fill weights: 4 ci x 27 k x 64 co (float4 vectorized) ---
        {
            const float4* wg = (const float4*)w;
            float4* ws = (float4*)wsm;
            for (int i = t; i < 1728; i += 256) {
                int ci = i / 432, r = i - ci * 432;
                int koff = r >> 4, j = r & 15;
                ws[i] = wg[(koff * 64 + cb * 4 + ci) * 16 + j];
            }
        }
        // --- fill patch (duplicated): 4 ci x 3 z x 6 y x 36 x ---
        for (int i = t; i < 2592; i += 256) {
            int ci = i / 648, r = i - ci * 648;
            int kzz = r / 216, r2 = r - kzz * 216;
            int yy = r2 / 36, xx = r2 - yy * 36;
            int zz = z - 1 + kzz, y = y0 - 1 + yy, x = xx - 1;
            float v = 0.0f;
            if (zz >= 0 && zz < 32 && y >= 0 && y < 32 && x >= 0 && x < 32)
                v = in[inb + (size_t)(cb * 4 + ci) * NV + zz * 1024 + y * 32 + x];
            psm[i] = make_float2(v, v);
        }
        __syncthreads();

#pragma unroll 1
        for (int ci = 0; ci < 4; ci++) {
#pragma unroll 1
            for (int kz = 0; kz < 3; kz++) {
                unsigned wbase = wsm_s + (((ci * 27 + kz * 9) * 64 + cog * 8) << 2);
                unsigned pbase = psm_s + ((((ci * 3 + kz) * 6) * 36 + sx) << 3);
#pragma unroll
                for (int ky = 0; ky < 3; ky++) {
#pragma unroll
                    for (int kx = 0; kx < 3; kx++) {
                        unsigned long long w01, w23, w45, w67;
                        unsigned wa = wbase + (ky * 3 + kx) * 256;
                        asm("ld.shared.v2.u64 {%0,%1}, [%2];"
                            : "=l"(w01), "=l"(w23) : "r"(wa));
                        asm("ld.shared.v2.u64 {%0,%1}, [%2];"
                            : "=l"(w45), "=l"(w67) : "r"(wa + 16));
#pragma unroll
                        for (int sy = 0; sy < 4; sy++) {
                            unsigned long long bv;
                            asm("ld.shared.b64 %0, [%1];"
                                : "=l"(bv) : "r"(pbase + (((sy + ky) * 36 + kx) << 3)));
                            asm("fma.rn.f32x2 %0, %1, %2, %0;" : "+l"(acc[0 + sy]) : "l"(w01), "l"(bv));
                            asm("fma.rn.f32x2 %0, %1, %2, %0;" : "+l"(acc[4 + sy]) : "l"(w23), "l"(bv));
                            asm("fma.rn.f32x2 %0, %1, %2, %0;" : "+l"(acc[8 + sy]) : "l"(w45), "l"(bv));
                            asm("fma.rn.f32x2 %0, %1, %2, %0;" : "+l"(acc[12 + sy]) : "l"(w67), "l"(bv));
                        }
                    }
                }
            }
        }
        __syncthreads();
    }

    // --- epilogue: unpack, add bias, store ---
    size_t ob = inb + (size_t)(cog * 8) * NV + z * 1024 + y0 * 32 + sx;
#pragma unroll
    for (int p = 0; p < 4; p++) {
        float b0 = bias[cog * 8 + p * 2], b1 = bias[cog * 8 + p * 2 + 1];
#pragma unroll
        for (int sy = 0; sy < 4; sy++) {
            float lo, hi;
            asm("mov.b64 {%0,%1}, %2;" : "=f"(lo), "=f"(hi) : "l"(acc[p * 4 + sy]));
            out[ob + (size_t)(p * 2) * NV + sy * 32] = lo + b0;
            out[ob + (size_t)(p * 2 + 1) * NV + sy * 32] = hi + b1;
        }
    }
}

// ---------------- BN stats over [b][c][v] (per channel) --------------------
__global__ void bnstats(const float* __restrict__ x, float* __restrict__ sum,
                        float* __restrict__ sumsq) {
    int c = blockIdx.x, b = blockIdx.y, t = threadIdx.x;
    const float* p = x + ((size_t)b * CC + c) * NV;
    float s = 0, q = 0;
    for (int i = t; i < NV; i += 256) {
        float v = p[i];
        s += v; q += v * v;
    }
    __shared__ float rs[256], rq[256];
    rs[t] = s; rq[t] = q;
    __syncthreads();
    for (int o = 128; o > 0; o >>= 1) {
        if (t < o) { rs[t] += rs[t + o]; rq[t] += rq[t + o]; }
        __syncthreads();
    }
    if (t == 0) { atomicAdd(&sum[c], rs[0]); atomicAdd(&sumsq[c], rq[0]); }
}

// ---------------- BN apply + LeakyReLU (in-place, [b][c][v]) ---------------
__global__ void bnapply(float* x, const float* __restrict__ gamma, const float* __restrict__ beta,
                        const float* __restrict__ sum, const float* __restrict__ sumsq,
                        float invcnt) {
    size_t i4 = (size_t)blockIdx.x * blockDim.x + threadIdx.x;  // exact grid
    int c = (int)((i4 * 4 / NV) % CC);
    float mean = sum[c] * invcnt;
    float var = sumsq[c] * invcnt - mean * mean;
    float sc = gamma[c] * rsqrtf(var + BNEPS);
    float sh = beta[c] - mean * sc;
    float4* p = (float4*)x;
    float4 v = p[i4];
    float u;
    u = v.x * sc + sh; v.x = u >= 0 ? u : ALPHA * u;
    u = v.y * sc + sh; v.y = u >= 0 ? u : ALPHA * u;
    u = v.z * sc + sh; v.z = u >= 0 ? u : ALPHA * u;
    u = v.w * sc + sh; v.w = u >= 0 ? u : ALPHA * u;
    p[i4] = v;
}

// ---------------- BN apply + LeakyReLU + transpose to [b][v][c] ------------
__global__ void bnapply_T(const float* __restrict__ x, const float* __restrict__ gamma,
                          const float* __restrict__ beta, const float* __restrict__ sum,
                          const float* __restrict__ sumsq, float invcnt,
                          float* __restrict__ vT) {
    __shared__ float s[CC][33];
    int b = blockIdx.y;
    int v0 = blockIdx.x * 32;
    int t = threadIdx.x;
    for (int i = t; i < 32 * 64; i += 256) {
        int c = i >> 5, v = i & 31;
        float mean = sum[c] * invcnt;
        float var = sumsq[c] * invcnt - mean * mean;
        float sc = gamma[c] * rsqrtf(var + BNEPS);
        float sh = beta[c] - mean * sc;
        float u = x[((size_t)b * CC + c) * NV + v0 + v] * sc + sh;
        s[c][v] = u >= 0 ? u : ALPHA * u;
    }
    __syncthreads();
    for (int i = t; i < 32 * 64; i += 256) {
        int v = i >> 6, c = i & 63;
        vT[((size_t)b * NV + v0 + v) * CC + c] = s[c][v];
    }
}

// ---------------- point branch GEMM: p[b][n][d] = feat[b][:,n] . W ---------
__global__ void pgemm(const float* __restrict__ feat, const float* __restrict__ w,
                      const float* __restrict__ bias, float* __restrict__ pT) {
    __shared__ float wsm[64 * 64];
    int b = blockIdx.y;
    int n = blockIdx.x * 256 + threadIdx.x;
    int t = threadIdx.x;
    for (int i = t; i < 4096; i += 256) wsm[i] = w[i];
    __syncthreads();
    float a[64];
#pragma unroll
    for (int j = 0; j < 64; j++) a[j] = 0.0f;
    for (int c = 0; c < 64; c++) {
        float f = feat[((size_t)b * CC + c) * NP + n];
        const float4* wr = (const float4*)&wsm[c * 64];
#pragma unroll
        for (int j = 0; j < 16; j++) {
            float4 w4 = wr[j];
            a[4 * j + 0] += f * w4.x;
            a[4 * j + 1] += f * w4.y;
            a[4 * j + 2] += f * w4.z;
            a[4 * j + 3] += f * w4.w;
        }
    }
    float4* o4 = (float4*)&pT[((size_t)b * NP + n) * CC];
#pragma unroll
    for (int j = 0; j < 16; j++) {
        float4 v;
        v.x = a[4 * j + 0] + bias[4 * j + 0];
        v.y = a[4 * j + 1] + bias[4 * j + 1];
        v.z = a[4 * j + 2] + bias[4 * j + 2];
        v.w = a[4 * j + 3] + bias[4 * j + 3];
        o4[j] = v;
    }
}

// ---------------- point-branch BN stats over [b][n][c] ---------------------
__global__ void pstats(const float* __restrict__ pT, float* __restrict__ sum,
                       float* __restrict__ sumsq) {
    int b = blockIdx.y, t = threadIdx.x;
    int c = t & 63, nl = t >> 6;
    int n0 = blockIdx.x * 256;
    float s = 0, q = 0;
    for (int n = n0 + nl; n < n0 + 256; n += 4) {
        float v = pT[((size_t)b * NP + n) * CC + c];
        s += v; q += v * v;
    }
    __shared__ float rs[256], rq[256];
    rs[t] = s; rq[t] = q;
    __syncthreads();
    if (t < 64) {
        s = rs[t] + rs[t + 64] + rs[t + 128] + rs[t + 192];
        q = rq[t] + rq[t + 64] + rq[t + 128] + rq[t + 192];
        atomicAdd(&sum[c], s);
        atomicAdd(&sumsq[c], q);
    }
}

// ---------------- final: devoxelize + BN(p)+lrelu + add, write [b][c][n] ---
__global__ void final_k(const float* __restrict__ vT, const float* __restrict__ pT,
                        const float* __restrict__ normc, const float* __restrict__ gamma,
                        const float* __restrict__ beta, const float* __restrict__ sum,
                        const float* __restrict__ sumsq, float* __restrict__ out) {
    __shared__ float res[64][65];
    __shared__ int cidx[64][8];
    __shared__ float cw[64][8];
    int b = blockIdx.y;
    int n0 = blockIdx.x * 64;
    int t = threadIdx.x;

    if (t < 64) {
        int n = n0 + t;
        float xs = normc[(b * 3 + 0) * NP + n];
        float ys = normc[(b * 3 + 1) * NP + n];
        float zs = normc[(b * 3 + 2) * NP + n];
        float x0f = floorf(xs), y0f = floorf(ys), z0f = floorf(zs);
        float fx = xs - x0f, fy = ys - y0f, fz = zs - z0f;
        int x0 = (int)x0f, y0 = (int)y0f, z0 = (int)z0f;
        int x1 = min(x0 + 1, 31), y1 = min(y0 + 1, 31), z1 = min(z0 + 1, 31);
#pragma unroll
        for (int k = 0; k < 8; k++) {
            int dx = (k >> 2) & 1, dy = (k >> 1) & 1, dz = k & 1;
            float wt = (dx ? fx : 1.0f - fx) * (dy ? fy : 1.0f - fy) * (dz ? fz : 1.0f - fz);
            int idx = ((dx ? x1 : x0) * 32 + (dy ? y1 : y0)) * 32 + (dz ? z1 : z0);
            cidx[t][k] = idx;
            cw[t][k] = wt;
        }
    }
    __syncthreads();

    int c = t & 63, ty = t >> 6;
    float invc = 1.0f / (float)(BB * NP);
    float mean = sum[c] * invc;
    float var = sumsq[c] * invc - mean * mean;
    float sc = gamma[c] * rsqrtf(var + BNEPS);
    float sh = beta[c] - mean * sc;

    for (int j = ty; j < 64; j += 4) {
        float acc = 0.0f;
#pragma unroll
        for (int k = 0; k < 8; k++)
            acc += cw[j][k] * vT[((size_t)b * NV + cidx[j][k]) * CC + c];
        float pv = pT[((size_t)b * NP + n0 + j) * CC + c] * sc + sh;
        pv = pv >= 0 ? pv : ALPHA * pv;
        res[c][j] = acc + pv;
    }
    __syncthreads();

    for (int i = t; i < 4096; i += 256) {
        int c2 = i >> 6, j = i & 63;
        out[((size_t)b * CC + c2) * NP + n0 + j] = res[c2][j];
    }
}

// ---------------- launcher ----------------
extern "C" void kernel_launch(void* const* d_in, const int* in_sizes, int n_in,
                              void* d_out, int out_size) {
    const float* feat   = (const float*)d_in[0];
    const float* coords = (const float*)d_in[1];
    const float* c1w    = (const float*)d_in[2];
    const float* c1b    = (const float*)d_in[3];
    const float* g1     = (const float*)d_in[4];
    const float* b1     = (const float*)d_in[5];
    const float* c2w    = (const float*)d_in[6];
    const float* c2b    = (const float*)d_in[7];
    const float* g2     = (const float*)d_in[8];
    const float* b2     = (const float*)d_in[9];
    const float* pw     = (const float*)d_in[10];
    const float* pb     = (const float*)d_in[11];
    const float* pg     = (const float*)d_in[12];
    const float* pbeta  = (const float*)d_in[13];
    float* out = (float*)d_out;

    float *fT, *tmp, *cnt, *bufA, *bufB, *pT, *normc, *cmean, *cmax, *sum, *sumsq;
    cudaGetSymbolAddress((void**)&fT, g_fT);
    cudaGetSymbolAddress((void**)&tmp, g_tmp);
    cudaGetSymbolAddress((void**)&cnt, g_cnt);
    cudaGetSymbolAddress((void**)&bufA, g_bufA);
    cudaGetSymbolAddress((void**)&bufB, g_bufB);
    cudaGetSymbolAddress((void**)&pT, g_pT);
    cudaGetSymbolAddress((void**)&normc, g_normc);
    cudaGetSymbolAddress((void**)&cmean, g_cmean);
    cudaGetSymbolAddress((void**)&cmax, g_cmax);
    cudaGetSymbolAddress((void**)&sum, g_sum);
    cudaGetSymbolAddress((void**)&sumsq, g_sumsq);

    // voxelize
    zero_kernel<<<8192, 256>>>(tmp, (size_t)BB * NV * CC);
    zero_kernel<<<256, 256>>>(cnt, (size_t)BB * NV);
    transpose_feat<<<dim3(NP / 32, BB), 256>>>(feat, fT);
    coord_mean<<<BB, 256>>>(coords, cmean);
    coord_max<<<BB, 256>>>(coords, cmean, cmax);
    scatter<<<BB * NP / 4, 256>>>(coords, fT, cmean, cmax, normc, tmp, cnt);
    finalize_vox<<<dim3(NV / 32, BB), 256>>>(tmp, cnt, bufA);

    // conv1 + BN + lrelu
    conv3d_v2<<<dim3(8, 32, BB), 256>>>(bufA, bufB, c1w, c1b);
    zero_stats<<<1, 64>>>(sum, sumsq);
    bnstats<<<dim3(CC, BB), 256>>>(bufB, sum, sumsq);
    bnapply<<<(BB * CC * NV / 4) / 256, 256>>>(bufB, g1, b1, sum, sumsq, 1.0f / (float)(BB * NV));

    // conv2 + BN + lrelu + transpose to [b][v][c] (reuse tmp as vT)
    conv3d_v2<<<dim3(8, 32, BB), 256>>>(bufB, bufA, c2w, c2b);
    zero_stats<<<1, 64>>>(sum, sumsq);
    bnstats<<<dim3(CC, BB), 256>>>(bufA, sum, sumsq);
    bnapply_T<<<dim3(NV / 32, BB), 256>>>(bufA, g2, b2, sum, sumsq, 1.0f / (float)(BB * NV), tmp);

    // point branch
    pgemm<<<dim3(NP / 256, BB), 256>>>(feat, pw, pb, pT);
    zero_stats<<<1, 64>>>(sum, sumsq);
    pstats<<<dim3(NP / 256, BB), 256>>>(pT, sum, sumsq);

    // devoxelize + point BN + add
    final_k<<<dim3(NP / 64, BB), 256>>>(tmp, pT, normc, pg, pbeta, sum, sumsq, out);

    // coords passthrough (second tuple output), if the harness expects it
    int main_sz = BB * CC * NP;
    int coord_sz = BB * 3 * NP;
    if (out_size >= main_sz + coord_sz)
        copy_kernel<<<coord_sz / 256, 256>>>(coords, out + main_sz, coord_sz);
}

// round 5
// speedup vs baseline: 4.6271x; 1.1193x over previous
#include <cuda_runtime.h>

#define BB 8
#define CC 64
#define NP 16384
#define RR 32
#define NV 32768          // 32^3
#define ALPHA 0.1f
#define BNEPS 1e-4f
#define VOXEPS 1e-6f

// ---------------- scratch (device globals; no allocation allowed) ----------
__device__ float g_fT[BB * NP * CC];        // features transposed [b][n][c]
__device__ float g_tmp[BB * NV * CC];       // voxel sums [b][v][c]; later vT
__device__ float g_cnt[BB * NV];            // voxel counts
__device__ float g_bufA[BB * CC * NV];      // channel-major grid buffers
__device__ float g_bufB[BB * CC * NV];
__device__ float g_pT[BB * NP * CC];        // point branch [b][n][c]
__device__ float g_normc[BB * 3 * NP];      // normalized coords in [0,31]
__device__ float g_cmean[BB * 3];           // coordinate SUMS (divide by NP on use)
__device__ unsigned g_cmaxb[BB];            // max dist^2 as float bits
__device__ float g_stats[6 * CC];           // sum1,sq1,sum2,sq2,psum,psq
__device__ float g_scsh[6 * CC];            // sc1,sh1,sc2,sh2,scp,shp

// ---------------- utility kernels ----------------
__global__ void zero_kernel(float* p, size_t n) {
    size_t i = (size_t)blockIdx.x * blockDim.x + threadIdx.x;
    size_t stride = (size_t)gridDim.x * blockDim.x;
    for (; i < n; i += stride) p[i] = 0.0f;
}

__global__ void zero_small(float* stats, float* cmean, unsigned* cmaxb) {
    int t = threadIdx.x;
    if (t < 6 * CC) stats[t] = 0.0f;
    if (t < BB * 3) cmean[t] = 0.0f;
    if (t < BB) cmaxb[t] = 0u;
}

__global__ void copy_kernel(const float* __restrict__ src, float* __restrict__ dst, int n) {
    int i = blockIdx.x * blockDim.x + threadIdx.x;
    int stride = gridDim.x * blockDim.x;
    for (; i < n; i += stride) dst[i] = src[i];
}

// turn (sum, sumsq) into (scale, shift)
__global__ void mkscale(const float* __restrict__ sum, const float* __restrict__ sumsq,
                        const float* __restrict__ gamma, const float* __restrict__ beta,
                        float invcnt, float* __restrict__ sc, float* __restrict__ sh) {
    int c = threadIdx.x;
    float mean = sum[c] * invcnt;
    float var = sumsq[c] * invcnt - mean * mean;
    float s = gamma[c] * rsqrtf(var + BNEPS);
    sc[c] = s;
    sh[c] = beta[c] - mean * s;
}

// ---------------- features transpose [b][c][n] -> [b][n][c] ----------------
__global__ void transpose_feat(const float* __restrict__ feat, float* __restrict__ fT) {
    __shared__ float s[CC][33];
    int b = blockIdx.y;
    int n0 = blockIdx.x * 32;
    int t = threadIdx.x;
    for (int i = t; i < 32 * 64; i += 256) {
        int c = i >> 5, n = i & 31;
        s[c][n] = feat[(b * CC + c) * NP + n0 + n];
    }
    __syncthreads();
    for (int i = t; i < 32 * 64; i += 256) {
        int n = i >> 6, c = i & 63;
        fT[((size_t)b * NP + n0 + n) * CC + c] = s[c][n];
    }
}

// ---------------- coord statistics (parallel partials + atomics) -----------
__global__ void coord_mean_p(const float* __restrict__ coords, float* __restrict__ cmean) {
    int b = blockIdx.y;
    int n0 = blockIdx.x * 512;
    int t = threadIdx.x;
    float s0 = 0, s1 = 0, s2 = 0;
    for (int n = n0 + t; n < n0 + 512; n += 256) {
        s0 += coords[(b * 3 + 0) * NP + n];
        s1 += coords[(b * 3 + 1) * NP + n];
        s2 += coords[(b * 3 + 2) * NP + n];
    }
#pragma unroll
    for (int o = 16; o > 0; o >>= 1) {
        s0 += __shfl_xor_sync(0xffffffff, s0, o);
        s1 += __shfl_xor_sync(0xffffffff, s1, o);
        s2 += __shfl_xor_sync(0xffffffff, s2, o);
    }
    if ((t & 31) == 0) {
        atomicAdd(&cmean[b * 3 + 0], s0);
        atomicAdd(&cmean[b * 3 + 1], s1);
        atomicAdd(&cmean[b * 3 + 2], s2);
    }
}

__global__ void coord_max_p(const float* __restrict__ coords, const float* __restrict__ cmean,
                            unsigned* __restrict__ cmaxb) {
    int b = blockIdx.y;
    int n0 = blockIdx.x * 512;
    int t = threadIdx.x;
    float invn = 1.0f / (float)NP;
    float mx = cmean[b * 3 + 0] * invn, my = cmean[b * 3 + 1] * invn, mz = cmean[b * 3 + 2] * invn;
    float m = 0.0f;
    for (int n = n0 + t; n < n0 + 512; n += 256) {
        float dx = coords[(b * 3 + 0) * NP + n] - mx;
        float dy = coords[(b * 3 + 1) * NP + n] - my;
        float dz = coords[(b * 3 + 2) * NP + n] - mz;
        m = fmaxf(m, dx * dx + dy * dy + dz * dz);
    }
#pragma unroll
    for (int o = 16; o > 0; o >>= 1) m = fmaxf(m, __shfl_xor_sync(0xffffffff, m, o));
    if ((t & 31) == 0) atomicMax(&cmaxb[b], __float_as_uint(m));
}

// ---------------- voxelize scatter (4 points per block, 64 threads/point) --
__global__ void scatter(const float* __restrict__ coords, const float* __restrict__ fT,
                        const float* __restrict__ cmean, const unsigned* __restrict__ cmaxb,
                        float* __restrict__ normc, float* __restrict__ tmp,
                        float* __restrict__ cnt) {
    int t = threadIdx.x;
    int pi = blockIdx.x * 4 + (t >> 6);
    int c = t & 63;
    int b = pi / NP;
    int n = pi - b * NP;

    float invn = 1.0f / (float)NP;
    float r = sqrtf(__uint_as_float(cmaxb[b]));
    float inv = 1.0f / (2.0f * r + VOXEPS);
    float nx = (coords[(b * 3 + 0) * NP + n] - cmean[b * 3 + 0] * invn) * inv + 0.5f;
    float ny = (coords[(b * 3 + 1) * NP + n] - cmean[b * 3 + 1] * invn) * inv + 0.5f;
    float nz = (coords[(b * 3 + 2) * NP + n] - cmean[b * 3 + 2] * invn) * inv + 0.5f;
    nx = fminf(fmaxf(nx * (float)RR, 0.0f), (float)(RR - 1));
    ny = fminf(fmaxf(ny * (float)RR, 0.0f), (float)(RR - 1));
    nz = fminf(fmaxf(nz * (float)RR, 0.0f), (float)(RR - 1));
    int vx = __float2int_rn(nx), vy = __float2int_rn(ny), vz = __float2int_rn(nz);
    int v = (vx * RR + vy) * RR + vz;

    float f = fT[((size_t)b * NP + n) * CC + c];
    atomicAdd(&tmp[((size_t)b * NV + v) * CC + c], f);
    if (c == 0) atomicAdd(&cnt[b * NV + v], 1.0f);
    if (c < 3) normc[(b * 3 + c) * NP + n] = (c == 0 ? nx : (c == 1 ? ny : nz));
}

// ---------------- finalize: [b][v][c]/count -> [b][c][v] -------------------
__global__ void finalize_vox(const float* __restrict__ tmp, const float* __restrict__ cnt,
                             float* __restrict__ grid) {
    __shared__ float s[CC][33];
    __shared__ float cs[32];
    int b = blockIdx.y;
    int v0 = blockIdx.x * 32;
    int t = threadIdx.x;
    for (int i = t; i < 32 * 64; i += 256) {
        int v = i >> 6, c = i & 63;
        s[c][v] = tmp[((size_t)b * NV + v0 + v) * CC + c];
    }
    if (t < 32) cs[t] = fmaxf(cnt[b * NV + v0 + t], 1.0f);
    __syncthreads();
    for (int i = t; i < 32 * 64; i += 256) {
        int c = i >> 5, v = i & 31;
        grid[((size_t)b * CC + c) * NV + v0 + v] = s[c][v] / cs[v];
    }
}

// ---------------- 3^3 conv v3: FFMA2 + software pipeline + fused BN --------
// Block: 64 c_out x (4y x 32x), fixed (z,b). 256 threads, 2 blocks/SM.
// Double-buffered dynamic smem; register prefetch of next ci-chunk.
// APPLY: transform input by lrelu(x*sc+sh) (BN of previous stage) at fill time.
//        NOTE: sc/sh are indexed by GLOBAL channel cb*4 + pci.
// Epilogue: bias add + per-channel sum/sumsq partial reduction -> global atomics.
#define WBYTES 27648
#define PBYTES 20736
template <bool APPLY>
__global__ __launch_bounds__(256, 2) void conv3d_v3(
    const float* __restrict__ in, float* __restrict__ out,
    const float* __restrict__ w, const float* __restrict__ bias,
    const float* __restrict__ insc, const float* __restrict__ insh,
    float* __restrict__ gsum, float* __restrict__ gsumsq) {
    extern __shared__ __align__(16) float dsm[];
    __shared__ float sc_sm[64], sh_sm[64];

    int b = blockIdx.z, z = blockIdx.y, y0 = blockIdx.x * 4;
    int t = threadIdx.x;
    int sx = t & 31, cog = t >> 5, lane = t & 31;

    if (APPLY) {
        if (t < 64) { sc_sm[t] = insc[t]; sh_sm[t] = insh[t]; }
        __syncthreads();   // visible to ALL threads before first do_sts
    }

    // invariant index precomputation
    int woff[7];
#pragma unroll
    for (int j = 0; j < 7; j++) {
        int idx = t + 256 * j;
        if (idx >= 1728) idx = 0;
        int ci = idx / 432, r = idx - ci * 432;
        int koff = r >> 4, jj = r & 15;
        woff[j] = (koff * 64 + ci) * 16 + jj;   // float4 index (before cb offset)
    }
    int poff[11], pci[11];
    bool pok[11];
#pragma unroll
    for (int j = 0; j < 11; j++) {
        int idx = t + 256 * j;
        bool inr = idx < 2592;
        int ii = inr ? idx : 0;
        int ci = ii / 648, r = ii - ci * 648;
        int kzz = r / 216, r2 = r - kzz * 216;
        int yy = r2 / 36, xx = r2 - yy * 36;
        int zz = z - 1 + kzz, y = y0 - 1 + yy, x = xx - 1;
        pok[j] = inr && zz >= 0 && zz < 32 && y >= 0 && y < 32 && x >= 0 && x < 32;
        poff[j] = zz * 1024 + y * 32 + x;
        pci[j] = ci;
    }

    const float* inb = in + (size_t)b * CC * NV;
    const float4* wg = (const float4*)w;
    unsigned smem_u = (unsigned)__cvta_generic_to_shared(dsm);

    unsigned long long acc[16];
#pragma unroll
    for (int i = 0; i < 16; i++) acc[i] = 0ULL;

    float4 wreg[7];
    float preg[11];

    auto prefetch = [&](int cb) {
#pragma unroll
        for (int j = 0; j < 7; j++)
            if (j < 6 || t < 192) wreg[j] = wg[woff[j] + cb * 64];
#pragma unroll
        for (int j = 0; j < 11; j++)
            preg[j] = pok[j] ? __ldg(inb + (size_t)(cb * 4 + pci[j]) * NV + poff[j]) : 0.0f;
    };
    // cb = which ci-chunk this data belongs to (for GLOBAL channel BN indexing)
    auto do_sts = [&](int buf, int cb) {
        float4* wd = (float4*)(dsm + buf * (WBYTES / 4));
        float2* pd = (float2*)(dsm + 2 * (WBYTES / 4) + buf * (PBYTES / 4));
#pragma unroll
        for (int j = 0; j < 7; j++)
            if (j < 6 || t < 192) wd[t + 256 * j] = wreg[j];
#pragma unroll
        for (int j = 0; j < 11; j++) {
            if (j < 10 || t < 32) {
                float v = preg[j];
                if (APPLY) {
                    int cg = cb * 4 + pci[j];   // GLOBAL input channel
                    float u = fmaf(v, sc_sm[cg], sh_sm[cg]);
                    v = u >= 0 ? u : ALPHA * u;
                    if (!pok[j]) v = 0.0f;      // zero padding AFTER transform
                }
                pd[t + 256 * j] = make_float2(v, v);
            }
        }
    };
    auto compute = [&](int buf) {
        unsigned wbuf = smem_u + buf * WBYTES;
        unsigned pbuf = smem_u + 2 * WBYTES + buf * PBYTES;
#pragma unroll 1
        for (int ci = 0; ci < 4; ci++) {
#pragma unroll 1
            for (int kz = 0; kz < 3; kz++) {
                unsigned wbase = wbuf + (((ci * 27 + kz * 9) * 64 + cog * 8) << 2);
                unsigned pbase = pbuf + ((((ci * 3 + kz) * 6) * 36 + sx) << 3);
#pragma unroll
                for (int ky = 0; ky < 3; ky++) {
#pragma unroll
                    for (int kx = 0; kx < 3; kx++) {
                        unsigned long long w01, w23, w45, w67;
                        unsigned wa = wbase + (ky * 3 + kx) * 256;
                        asm("ld.shared.v2.u64 {%0,%1}, [%2];" : "=l"(w01), "=l"(w23) : "r"(wa));
                        asm("ld.shared.v2.u64 {%0,%1}, [%2];" : "=l"(w45), "=l"(w67) : "r"(wa + 16));
#pragma unroll
                        for (int sy = 0; sy < 4; sy++) {
                            unsigned long long bv;
                            asm("ld.shared.b64 %0, [%1];"
                                : "=l"(bv) : "r"(pbase + (((sy + ky) * 36 + kx) << 3)));
                            asm("fma.rn.f32x2 %0, %1, %2, %0;" : "+l"(acc[0 + sy]) : "l"(w01), "l"(bv));
                            asm("fma.rn.f32x2 %0, %1, %2, %0;" : "+l"(acc[4 + sy]) : "l"(w23), "l"(bv));
                            asm("fma.rn.f32x2 %0, %1, %2, %0;" : "+l"(acc[8 + sy]) : "l"(w45), "l"(bv));
                            asm("fma.rn.f32x2 %0, %1, %2, %0;" : "+l"(acc[12 + sy]) : "l"(w67), "l"(bv));
                        }
                    }
                }
            }
        }
    };

    prefetch(0);
    do_sts(0, 0);
    __syncthreads();
#pragma unroll 1
    for (int cb = 0; cb < 16; cb++) {
        if (cb < 15) prefetch(cb + 1);
        compute(cb & 1);
        if (cb < 15) {
            do_sts((cb + 1) & 1, cb + 1);
            __syncthreads();
        }
    }

    // epilogue: bias add + store + per-channel stats
    float sv[8], qv[8];
    size_t ob = (size_t)b * CC * NV + (size_t)(cog * 8) * NV + z * 1024 + y0 * 32 + sx;
#pragma unroll
    for (int p = 0; p < 4; p++) {
        float b0 = bias[cog * 8 + p * 2], b1 = bias[cog * 8 + p * 2 + 1];
        float s0 = 0, q0 = 0, s1 = 0, q1 = 0;
#pragma unroll
        for (int sy = 0; sy < 4; sy++) {
            float lo, hi;
            asm("mov.b64 {%0,%1}, %2;" : "=f"(lo), "=f"(hi) : "l"(acc[p * 4 + sy]));
            float olo = lo + b0, ohi = hi + b1;
            out[ob + (size_t)(p * 2) * NV + sy * 32] = olo;
            out[ob + (size_t)(p * 2 + 1) * NV + sy * 32] = ohi;
            s0 += olo; q0 += olo * olo;
            s1 += ohi; q1 += ohi * ohi;
        }
        sv[p * 2] = s0; qv[p * 2] = q0;
        sv[p * 2 + 1] = s1; qv[p * 2 + 1] = q1;
    }
#pragma unroll
    for (int o = 16; o > 0; o >>= 1) {
#pragma unroll
        for (int j = 0; j < 8; j++) {
            sv[j] += __shfl_xor_sync(0xffffffff, sv[j], o);
            qv[j] += __shfl_xor_sync(0xffffffff, qv[j], o);
        }
    }
    if (lane == 0) {
#pragma unroll
        for (int j = 0; j < 8; j++) {
            atomicAdd(&gsum[cog * 8 + j], sv[j]);
            atomicAdd(&gsumsq[cog * 8 + j], qv[j]);
        }
    }
}

// ---------------- BN apply + LeakyReLU + transpose to [b][v][c] ------------
__global__ void bnapply_T(const float* __restrict__ x, const float* __restrict__ sc,
                          const float* __restrict__ sh, float* __restrict__ vT) {
    __shared__ float s[CC][33];
    int b = blockIdx.y;
    int v0 = blockIdx.x * 32;
    int t = threadIdx.x;
    for (int i = t; i < 32 * 64; i += 256) {
        int c = i >> 5, v = i & 31;
        float u = fmaf(x[((size_t)b * CC + c) * NV + v0 + v], sc[c], sh[c]);
        s[c][v] = u >= 0 ? u : ALPHA * u;
    }
    __syncthreads();
    for (int i = t; i < 32 * 64; i += 256) {
        int v = i >> 6, c = i & 63;
        vT[((size_t)b * NV + v0 + v) * CC + c] = s[c][v];
    }
}

// ---------------- point branch GEMM: p[b][n][d] = feat[b][:,n] . W ---------
__global__ void pgemm(const float* __restrict__ feat, const float* __restrict__ w,
                      const float* __restrict__ bias, float* __restrict__ pT) {
    __shared__ float wsm[64 * 64];
    int b = blockIdx.y;
    int n = blockIdx.x * 256 + threadIdx.x;
    int t = threadIdx.x;
    for (int i = t; i < 4096; i += 256) wsm[i] = w[i];
    __syncthreads();
    float a[64];
#pragma unroll
    for (int j = 0; j < 64; j++) a[j] = 0.0f;
    for (int c = 0; c < 64; c++) {
        float f = feat[((size_t)b * CC + c) * NP + n];
        const float4* wr = (const float4*)&wsm[c * 64];
#pragma unroll
        for (int j = 0; j < 16; j++) {
            float4 w4 = wr[j];
            a[4 * j + 0] += f * w4.x;
            a[4 * j + 1] += f * w4.y;
            a[4 * j + 2] += f * w4.z;
            a[4 * j + 3] += f * w4.w;
        }
    }
    float4* o4 = (float4*)&pT[((size_t)b * NP + n) * CC];
#pragma unroll
    for (int j = 0; j < 16; j++) {
        float4 v;
        v.x = a[4 * j + 0] + bias[4 * j + 0];
        v.y = a[4 * j + 1] + bias[4 * j + 1];
        v.z = a[4 * j + 2] + bias[4 * j + 2];
        v.w = a[4 * j + 3] + bias[4 * j + 3];
        o4[j] = v;
    }
}

// ---------------- point-branch BN stats over [b][n][c] ---------------------
__global__ void pstats(const float* __restrict__ pT, float* __restrict__ sum,
                       float* __restrict__ sumsq) {
    int b = blockIdx.y, t = threadIdx.x;
    int c = t & 63, nl = t >> 6;
    int n0 = blockIdx.x * 256;
    float s = 0, q = 0;
    for (int n = n0 + nl; n < n0 + 256; n += 4) {
        float v = pT[((size_t)b * NP + n) * CC + c];
        s += v; q += v * v;
    }
    __shared__ float rs[256], rq[256];
    rs[t] = s; rq[t] = q;
    __syncthreads();
    if (t < 64) {
        s = rs[t] + rs[t + 64] + rs[t + 128] + rs[t + 192];
        q = rq[t] + rq[t + 64] + rq[t + 128] + rq[t + 192];
        atomicAdd(&sum[c], s);
        atomicAdd(&sumsq[c], q);
    }
}

// ---------------- final: devoxelize + BN(p)+lrelu + add, write [b][c][n] ---
__global__ void final_k(const float* __restrict__ vT, const float* __restrict__ pT,
                        const float* __restrict__ normc, const float* __restrict__ sc,
                        const float* __restrict__ sh, float* __restrict__ out) {
    __shared__ float res[64][65];
    __shared__ int cidx[64][8];
    __shared__ float cw[64][8];
    int b = blockIdx.y;
    int n0 = blockIdx.x * 64;
    int t = threadIdx.x;

    if (t < 64) {
        int n = n0 + t;
        float xs = normc[(b * 3 + 0) * NP + n];
        float ys = normc[(b * 3 + 1) * NP + n];
        float zs = normc[(b * 3 + 2) * NP + n];
        float x0f = floorf(xs), y0f = floorf(ys), z0f = floorf(zs);
        float fx = xs - x0f, fy = ys - y0f, fz = zs - z0f;
        int x0 = (int)x0f, y0 = (int)y0f, z0 = (int)z0f;
        int x1 = min(x0 + 1, 31), y1 = min(y0 + 1, 31), z1 = min(z0 + 1, 31);
#pragma unroll
        for (int k = 0; k < 8; k++) {
            int dx = (k >> 2) & 1, dy = (k >> 1) & 1, dz = k & 1;
            float wt = (dx ? fx : 1.0f - fx) * (dy ? fy : 1.0f - fy) * (dz ? fz : 1.0f - fz);
            int idx = ((dx ? x1 : x0) * 32 + (dy ? y1 : y0)) * 32 + (dz ? z1 : z0);
            cidx[t][k] = idx;
            cw[t][k] = wt;
        }
    }
    __syncthreads();

    int c = t & 63, ty = t >> 6;
    float scv = sc[c], shv = sh[c];

    for (int j = ty; j < 64; j += 4) {
        float acc = 0.0f;
#pragma unroll
        for (int k = 0; k < 8; k++)
            acc += cw[j][k] * vT[((size_t)b * NV + cidx[j][k]) * CC + c];
        float pv = fmaf(pT[((size_t)b * NP + n0 + j) * CC + c], scv, shv);
        pv = pv >= 0 ? pv : ALPHA * pv;
        res[c][j] = acc + pv;
    }
    __syncthreads();

    for (int i = t; i < 4096; i += 256) {
        int c2 = i >> 6, j = i & 63;
        out[((size_t)b * CC + c2) * NP + n0 + j] = res[c2][j];
    }
}

// ---------------- launcher ----------------
extern "C" void kernel_launch(void* const* d_in, const int* in_sizes, int n_in,
                              void* d_out, int out_size) {
    const float* feat   = (const float*)d_in[0];
    const float* coords = (const float*)d_in[1];
    const float* c1w    = (const float*)d_in[2];
    const float* c1b    = (const float*)d_in[3];
    const float* g1     = (const float*)d_in[4];
    const float* b1     = (const float*)d_in[5];
    const float* c2w    = (const float*)d_in[6];
    const float* c2b    = (const float*)d_in[7];
    const float* g2     = (const float*)d_in[8];
    const float* b2     = (const float*)d_in[9];
    const float* pw     = (const float*)d_in[10];
    const float* pb     = (const float*)d_in[11];
    const float* pg     = (const float*)d_in[12];
    const float* pbeta  = (const float*)d_in[13];
    float* out = (float*)d_out;

    float *fT, *tmp, *cnt, *bufA, *bufB, *pT, *normc, *cmean, *stats, *scsh;
    unsigned* cmaxb;
    cudaGetSymbolAddress((void**)&fT, g_fT);
    cudaGetSymbolAddress((void**)&tmp, g_tmp);
    cudaGetSymbolAddress((void**)&cnt, g_cnt);
    cudaGetSymbolAddress((void**)&bufA, g_bufA);
    cudaGetSymbolAddress((void**)&bufB, g_bufB);
    cudaGetSymbolAddress((void**)&pT, g_pT);
    cudaGetSymbolAddress((void**)&normc, g_normc);
    cudaGetSymbolAddress((void**)&cmean, g_cmean);
    cudaGetSymbolAddress((void**)&cmaxb, g_cmaxb);
    cudaGetSymbolAddress((void**)&stats, g_stats);
    cudaGetSymbolAddress((void**)&scsh, g_scsh);

    float* sum1 = stats + 0 * CC;  float* sq1 = stats + 1 * CC;
    float* sum2 = stats + 2 * CC;  float* sq2 = stats + 3 * CC;
    float* psum = stats + 4 * CC;  float* psq = stats + 5 * CC;
    float* sc1 = scsh + 0 * CC;    float* sh1 = scsh + 1 * CC;
    float* sc2 = scsh + 2 * CC;    float* sh2 = scsh + 3 * CC;
    float* scp = scsh + 4 * CC;    float* shp = scsh + 5 * CC;

    int dyn = 2 * WBYTES + 2 * PBYTES;  // 96768 B
    cudaFuncSetAttribute(conv3d_v3<false>, cudaFuncAttributeMaxDynamicSharedMemorySize, dyn);
    cudaFuncSetAttribute(conv3d_v3<true>,  cudaFuncAttributeMaxDynamicSharedMemorySize, dyn);

    const float invV = 1.0f / (float)(BB * NV);
    const float invP = 1.0f / (float)(BB * NP);

    // voxelize
    zero_kernel<<<8192, 256>>>(tmp, (size_t)BB * NV * CC);
    zero_kernel<<<256, 256>>>(cnt, (size_t)BB * NV);
    zero_small<<<1, 512>>>(stats, cmean, cmaxb);
    transpose_feat<<<dim3(NP / 32, BB), 256>>>(feat, fT);
    coord_mean_p<<<dim3(32, BB), 256>>>(coords, cmean);
    coord_max_p<<<dim3(32, BB), 256>>>(coords, cmean, cmaxb);
    scatter<<<BB * NP / 4, 256>>>(coords, fT, cmean, cmaxb, normc, tmp, cnt);
    finalize_vox<<<dim3(NV / 32, BB), 256>>>(tmp, cnt, bufA);

    // conv1 (+ fused stats)
    conv3d_v3<false><<<dim3(8, 32, BB), 256, dyn>>>(bufA, bufB, c1w, c1b,
                                                    nullptr, nullptr, sum1, sq1);
    mkscale<<<1, 64>>>(sum1, sq1, g1, b1, invV, sc1, sh1);

    // conv2 (input BN1+lrelu fused into patch load; + fused stats)
    conv3d_v3<true><<<dim3(8, 32, BB), 256, dyn>>>(bufB, bufA, c2w, c2b,
                                                   sc1, sh1, sum2, sq2);
    mkscale<<<1, 64>>>(sum2, sq2, g2, b2, invV, sc2, sh2);

    // BN2 apply + lrelu + transpose to [b][v][c] (reuse tmp as vT)
    bnapply_T<<<dim3(NV / 32, BB), 256>>>(bufA, sc2, sh2, tmp);

    // point branch
    pgemm<<<dim3(NP / 256, BB), 256>>>(feat, pw, pb, pT);
    pstats<<<dim3(NP / 256, BB), 256>>>(pT, psum, psq);
    mkscale<<<1, 64>>>(psum, psq, pg, pbeta, invP, scp, shp);

    // devoxelize + point BN + add
    final_k<<<dim3(NP / 64, BB), 256>>>(tmp, pT, normc, scp, shp, out);

    // coords passthrough (second tuple output), if the harness expects it
    int main_sz = BB * CC * NP;
    int coord_sz = BB * 3 * NP;
    if (out_size >= main_sz + coord_sz)
        copy_kernel<<<coord_sz / 256, 256>>>(coords, out + main_sz, coord_sz);
}

// round 6
// speedup vs baseline: 4.7819x; 1.0335x over previous
#include <cuda_runtime.h>

#define BB 8
#define CC 64
#define NP 16384
#define RR 32
#define NV 32768          // 32^3
#define ALPHA 0.1f
#define BNEPS 1e-4f
#define VOXEPS 1e-6f

// ---------------- scratch (device globals; no allocation allowed) ----------
__device__ float g_fT[BB * NP * CC];        // features transposed [b][n][c]
__device__ float g_tmp[BB * NV * CC];       // voxel sums [b][v][c]; later vT
__device__ float g_cnt[BB * NV];            // voxel counts
__device__ float g_bufA[BB * CC * NV];      // channel-major grid buffers
__device__ float g_bufB[BB * CC * NV];
__device__ float g_pT[BB * NP * CC];        // point branch [b][n][c]
__device__ float g_normc[BB * 3 * NP];      // normalized coords in [0,31]
__device__ float g_cmean[BB * 3];           // coordinate SUMS (divide by NP on use)
__device__ unsigned g_cmaxb[BB];            // max dist^2 as float bits
__device__ float g_stats[6 * CC];           // sum1,sq1,sum2,sq2,psum,psq
__device__ float g_scsh[6 * CC];            // sc1,sh1,sc2,sh2,scp,shp

// ---------------- utility kernels ----------------
__global__ void zero_kernel(float* p, size_t n) {
    size_t i = (size_t)blockIdx.x * blockDim.x + threadIdx.x;
    size_t stride = (size_t)gridDim.x * blockDim.x;
    for (; i < n; i += stride) p[i] = 0.0f;
}

__global__ void zero_small(float* stats, float* cmean, unsigned* cmaxb) {
    int t = threadIdx.x;
    if (t < 6 * CC) stats[t] = 0.0f;
    if (t < BB * 3) cmean[t] = 0.0f;
    if (t < BB) cmaxb[t] = 0u;
}

__global__ void copy_kernel(const float* __restrict__ src, float* __restrict__ dst, int n) {
    int i = blockIdx.x * blockDim.x + threadIdx.x;
    int stride = gridDim.x * blockDim.x;
    for (; i < n; i += stride) dst[i] = src[i];
}

// turn (sum, sumsq) into (scale, shift)
__global__ void mkscale(const float* __restrict__ sum, const float* __restrict__ sumsq,
                        const float* __restrict__ gamma, const float* __restrict__ beta,
                        float invcnt, float* __restrict__ sc, float* __restrict__ sh) {
    int c = threadIdx.x;
    float mean = sum[c] * invcnt;
    float var = sumsq[c] * invcnt - mean * mean;
    float s = gamma[c] * rsqrtf(var + BNEPS);
    sc[c] = s;
    sh[c] = beta[c] - mean * s;
}

// ---------------- features transpose [b][c][n] -> [b][n][c] ----------------
__global__ void transpose_feat(const float* __restrict__ feat, float* __restrict__ fT) {
    __shared__ float s[CC][33];
    int b = blockIdx.y;
    int n0 = blockIdx.x * 32;
    int t = threadIdx.x;
    for (int i = t; i < 32 * 64; i += 256) {
        int c = i >> 5, n = i & 31;
        s[c][n] = feat[(b * CC + c) * NP + n0 + n];
    }
    __syncthreads();
    for (int i = t; i < 32 * 64; i += 256) {
        int n = i >> 6, c = i & 63;
        fT[((size_t)b * NP + n0 + n) * CC + c] = s[c][n];
    }
}

// ---------------- coord statistics (parallel partials + atomics) -----------
__global__ void coord_mean_p(const float* __restrict__ coords, float* __restrict__ cmean) {
    int b = blockIdx.y;
    int n0 = blockIdx.x * 512;
    int t = threadIdx.x;
    float s0 = 0, s1 = 0, s2 = 0;
    for (int n = n0 + t; n < n0 + 512; n += 256) {
        s0 += coords[(b * 3 + 0) * NP + n];
        s1 += coords[(b * 3 + 1) * NP + n];
        s2 += coords[(b * 3 + 2) * NP + n];
    }
#pragma unroll
    for (int o = 16; o > 0; o >>= 1) {
        s0 += __shfl_xor_sync(0xffffffff, s0, o);
        s1 += __shfl_xor_sync(0xffffffff, s1, o);
        s2 += __shfl_xor_sync(0xffffffff, s2, o);
    }
    if ((t & 31) == 0) {
        atomicAdd(&cmean[b * 3 + 0], s0);
        atomicAdd(&cmean[b * 3 + 1], s1);
        atomicAdd(&cmean[b * 3 + 2], s2);
    }
}

__global__ void coord_max_p(const float* __restrict__ coords, const float* __restrict__ cmean,
                            unsigned* __restrict__ cmaxb) {
    int b = blockIdx.y;
    int n0 = blockIdx.x * 512;
    int t = threadIdx.x;
    float invn = 1.0f / (float)NP;
    float mx = cmean[b * 3 + 0] * invn, my = cmean[b * 3 + 1] * invn, mz = cmean[b * 3 + 2] * invn;
    float m = 0.0f;
    for (int n = n0 + t; n < n0 + 512; n += 256) {
        float dx = coords[(b * 3 + 0) * NP + n] - mx;
        float dy = coords[(b * 3 + 1) * NP + n] - my;
        float dz = coords[(b * 3 + 2) * NP + n] - mz;
        m = fmaxf(m, dx * dx + dy * dy + dz * dz);
    }
#pragma unroll
    for (int o = 16; o > 0; o >>= 1) m = fmaxf(m, __shfl_xor_sync(0xffffffff, m, o));
    if ((t & 31) == 0) atomicMax(&cmaxb[b], __float_as_uint(m));
}

// ---------------- voxelize scatter (4 points per block, 64 threads/point) --
__global__ void scatter(const float* __restrict__ coords, const float* __restrict__ fT,
                        const float* __restrict__ cmean, const unsigned* __restrict__ cmaxb,
                        float* __restrict__ normc, float* __restrict__ tmp,
                        float* __restrict__ cnt) {
    int t = threadIdx.x;
    int pi = blockIdx.x * 4 + (t >> 6);
    int c = t & 63;
    int b = pi / NP;
    int n = pi - b * NP;

    float invn = 1.0f / (float)NP;
    float r = sqrtf(__uint_as_float(cmaxb[b]));
    float inv = 1.0f / (2.0f * r + VOXEPS);
    float nx = (coords[(b * 3 + 0) * NP + n] - cmean[b * 3 + 0] * invn) * inv + 0.5f;
    float ny = (coords[(b * 3 + 1) * NP + n] - cmean[b * 3 + 1] * invn) * inv + 0.5f;
    float nz = (coords[(b * 3 + 2) * NP + n] - cmean[b * 3 + 2] * invn) * inv + 0.5f;
    nx = fminf(fmaxf(nx * (float)RR, 0.0f), (float)(RR - 1));
    ny = fminf(fmaxf(ny * (float)RR, 0.0f), (float)(RR - 1));
    nz = fminf(fmaxf(nz * (float)RR, 0.0f), (float)(RR - 1));
    int vx = __float2int_rn(nx), vy = __float2int_rn(ny), vz = __float2int_rn(nz);
    int v = (vx * RR + vy) * RR + vz;

    float f = fT[((size_t)b * NP + n) * CC + c];
    atomicAdd(&tmp[((size_t)b * NV + v) * CC + c], f);
    if (c == 0) atomicAdd(&cnt[b * NV + v], 1.0f);
    if (c < 3) normc[(b * 3 + c) * NP + n] = (c == 0 ? nx : (c == 1 ? ny : nz));
}

// ---------------- finalize: [b][v][c]/count -> [b][c][v] -------------------
__global__ void finalize_vox(const float* __restrict__ tmp, const float* __restrict__ cnt,
                             float* __restrict__ grid) {
    __shared__ float s[CC][33];
    __shared__ float cs[32];
    int b = blockIdx.y;
    int v0 = blockIdx.x * 32;
    int t = threadIdx.x;
    for (int i = t; i < 32 * 64; i += 256) {
        int v = i >> 6, c = i & 63;
        s[c][v] = tmp[((size_t)b * NV + v0 + v) * CC + c];
    }
    if (t < 32) cs[t] = fmaxf(cnt[b * NV + v0 + t], 1.0f);
    __syncthreads();
    for (int i = t; i < 32 * 64; i += 256) {
        int c = i >> 5, v = i & 31;
        grid[((size_t)b * CC + c) * NV + v0 + v] = s[c][v] / cs[v];
    }
}

// ---------------- 3^3 conv v4: FFMA2 + pipeline + fused BN + bv-reuse ------
// Inner loop restructured: per (ci,kz,kx) load 6 distinct B rows once,
// reuse across ky (bv[sy+ky]) -> halves B-operand smem traffic (was binding).
#define WBYTES 27648
#define PBYTES 20736
template <bool APPLY>
__global__ __launch_bounds__(256, 2) void conv3d_v4(
    const float* __restrict__ in, float* __restrict__ out,
    const float* __restrict__ w, const float* __restrict__ bias,
    const float* __restrict__ insc, const float* __restrict__ insh,
    float* __restrict__ gsum, float* __restrict__ gsumsq) {
    extern __shared__ __align__(16) float dsm[];
    __shared__ float sc_sm[64], sh_sm[64];

    int b = blockIdx.z, z = blockIdx.y, y0 = blockIdx.x * 4;
    int t = threadIdx.x;
    int sx = t & 31, cog = t >> 5, lane = t & 31;

    if (APPLY) {
        if (t < 64) { sc_sm[t] = insc[t]; sh_sm[t] = insh[t]; }
        __syncthreads();   // visible to ALL threads before first do_sts
    }

    // invariant index precomputation
    int woff[7];
#pragma unroll
    for (int j = 0; j < 7; j++) {
        int idx = t + 256 * j;
        if (idx >= 1728) idx = 0;
        int ci = idx / 432, r = idx - ci * 432;
        int koff = r >> 4, jj = r & 15;
        woff[j] = (koff * 64 + ci) * 16 + jj;   // float4 index (before cb offset)
    }
    int poff[11], pci[11];
    bool pok[11];
#pragma unroll
    for (int j = 0; j < 11; j++) {
        int idx = t + 256 * j;
        bool inr = idx < 2592;
        int ii = inr ? idx : 0;
        int ci = ii / 648, r = ii - ci * 648;
        int kzz = r / 216, r2 = r - kzz * 216;
        int yy = r2 / 36, xx = r2 - yy * 36;
        int zz = z - 1 + kzz, y = y0 - 1 + yy, x = xx - 1;
        pok[j] = inr && zz >= 0 && zz < 32 && y >= 0 && y < 32 && x >= 0 && x < 32;
        poff[j] = zz * 1024 + y * 32 + x;
        pci[j] = ci;
    }

    const float* inb = in + (size_t)b * CC * NV;
    const float4* wg = (const float4*)w;
    unsigned smem_u = (unsigned)__cvta_generic_to_shared(dsm);

    unsigned long long acc[16];
#pragma unroll
    for (int i = 0; i < 16; i++) acc[i] = 0ULL;

    float4 wreg[7];
    float preg[11];

    auto prefetch = [&](int cb) {
#pragma unroll
        for (int j = 0; j < 7; j++)
            if (j < 6 || t < 192) wreg[j] = wg[woff[j] + cb * 64];
#pragma unroll
        for (int j = 0; j < 11; j++)
            preg[j] = pok[j] ? __ldg(inb + (size_t)(cb * 4 + pci[j]) * NV + poff[j]) : 0.0f;
    };
    // cb = which ci-chunk this data belongs to (GLOBAL channel for BN indexing)
    auto do_sts = [&](int buf, int cb) {
        float4* wd = (float4*)(dsm + buf * (WBYTES / 4));
        float2* pd = (float2*)(dsm + 2 * (WBYTES / 4) + buf * (PBYTES / 4));
#pragma unroll
        for (int j = 0; j < 7; j++)
            if (j < 6 || t < 192) wd[t + 256 * j] = wreg[j];
#pragma unroll
        for (int j = 0; j < 11; j++) {
            if (j < 10 || t < 32) {
                float v = preg[j];
                if (APPLY) {
                    int cg = cb * 4 + pci[j];   // GLOBAL input channel
                    float u = fmaf(v, sc_sm[cg], sh_sm[cg]);
                    v = u >= 0 ? u : ALPHA * u;
                    if (!pok[j]) v = 0.0f;      // zero padding AFTER transform
                }
                pd[t + 256 * j] = make_float2(v, v);
            }
        }
    };
    auto compute = [&](int buf) {
        unsigned wbuf = smem_u + buf * WBYTES;
        unsigned pbuf = smem_u + 2 * WBYTES + buf * PBYTES;
#pragma unroll 1
        for (int ci = 0; ci < 4; ci++) {
#pragma unroll 1
            for (int kz = 0; kz < 3; kz++) {
                unsigned wbase = wbuf + (((ci * 27 + kz * 9) * 64 + cog * 8) << 2);
                unsigned pbase = pbuf + ((((ci * 3 + kz) * 6) * 36 + sx) << 3);
#pragma unroll
                for (int kx = 0; kx < 3; kx++) {
                    // load the 6 distinct B rows for this (kz,kx)
                    unsigned long long bv[6];
#pragma unroll
                    for (int r = 0; r < 6; r++) {
                        asm("ld.shared.b64 %0, [%1];"
                            : "=l"(bv[r]) : "r"(pbase + ((r * 36 + kx) << 3)));
                    }
#pragma unroll
                    for (int ky = 0; ky < 3; ky++) {
                        unsigned long long w01, w23, w45, w67;
                        unsigned wa = wbase + (ky * 3 + kx) * 256;
                        asm("ld.shared.v2.u64 {%0,%1}, [%2];" : "=l"(w01), "=l"(w23) : "r"(wa));
                        asm("ld.shared.v2.u64 {%0,%1}, [%2];" : "=l"(w45), "=l"(w67) : "r"(wa + 16));
#pragma unroll
                        for (int sy = 0; sy < 4; sy++) {
                            unsigned long long bvv = bv[sy + ky];
                            asm("fma.rn.f32x2 %0, %1, %2, %0;" : "+l"(acc[0 + sy]) : "l"(w01), "l"(bvv));
                            asm("fma.rn.f32x2 %0, %1, %2, %0;" : "+l"(acc[4 + sy]) : "l"(w23), "l"(bvv));
                            asm("fma.rn.f32x2 %0, %1, %2, %0;" : "+l"(acc[8 + sy]) : "l"(w45), "l"(bvv));
                            asm("fma.rn.f32x2 %0, %1, %2, %0;" : "+l"(acc[12 + sy]) : "l"(w67), "l"(bvv));
                        }
                    }
                }
            }
        }
    };

    prefetch(0);
    do_sts(0, 0);
    __syncthreads();
#pragma unroll 1
    for (int cb = 0; cb < 16; cb++) {
        if (cb < 15) prefetch(cb + 1);
        compute(cb & 1);
        if (cb < 15) {
            do_sts((cb + 1) & 1, cb + 1);
            __syncthreads();
        }
    }

    // epilogue: bias add + store + per-channel stats
    float sv[8], qv[8];
    size_t ob = (size_t)b * CC * NV + (size_t)(cog * 8) * NV + z * 1024 + y0 * 32 + sx;
#pragma unroll
    for (int p = 0; p < 4; p++) {
        float b0 = bias[cog * 8 + p * 2], b1 = bias[cog * 8 + p * 2 + 1];
        float s0 = 0, q0 = 0, s1 = 0, q1 = 0;
#pragma unroll
        for (int sy = 0; sy < 4; sy++) {
            float lo, hi;
            asm("mov.b64 {%0,%1}, %2;" : "=f"(lo), "=f"(hi) : "l"(acc[p * 4 + sy]));
            float olo = lo + b0, ohi = hi + b1;
            out[ob + (size_t)(p * 2) * NV + sy * 32] = olo;
            out[ob + (size_t)(p * 2 + 1) * NV + sy * 32] = ohi;
            s0 += olo; q0 += olo * olo;
            s1 += ohi; q1 += ohi * ohi;
        }
        sv[p * 2] = s0; qv[p * 2] = q0;
        sv[p * 2 + 1] = s1; qv[p * 2 + 1] = q1;
    }
#pragma unroll
    for (int o = 16; o > 0; o >>= 1) {
#pragma unroll
        for (int j = 0; j < 8; j++) {
            sv[j] += __shfl_xor_sync(0xffffffff, sv[j], o);
            qv[j] += __shfl_xor_sync(0xffffffff, qv[j], o);
        }
    }
    if (lane == 0) {
#pragma unroll
        for (int j = 0; j < 8; j++) {
            atomicAdd(&gsum[cog * 8 + j], sv[j]);
            atomicAdd(&gsumsq[cog * 8 + j], qv[j]);
        }
    }
}

// ---------------- BN apply + LeakyReLU + transpose to [b][v][c] ------------
__global__ void bnapply_T(const float* __restrict__ x, const float* __restrict__ sc,
                          const float* __restrict__ sh, float* __restrict__ vT) {
    __shared__ float s[CC][33];
    int b = blockIdx.y;
    int v0 = blockIdx.x * 32;
    int t = threadIdx.x;
    for (int i = t; i < 32 * 64; i += 256) {
        int c = i >> 5, v = i & 31;
        float u = fmaf(x[((size_t)b * CC + c) * NV + v0 + v], sc[c], sh[c]);
        s[c][v] = u >= 0 ? u : ALPHA * u;
    }
    __syncthreads();
    for (int i = t; i < 32 * 64; i += 256) {
        int v = i >> 6, c = i & 63;
        vT[((size_t)b * NV + v0 + v) * CC + c] = s[c][v];
    }
}

// ---------------- point branch GEMM (FFMA2): p[b][n][:] = feat[b][:,n].W ---
__global__ void pgemm(const float* __restrict__ feat, const float* __restrict__ w,
                      const float* __restrict__ bias, float* __restrict__ pT) {
    __shared__ __align__(16) float wsm[64 * 64];
    int b = blockIdx.y;
    int n = blockIdx.x * 256 + threadIdx.x;
    int t = threadIdx.x;
    for (int i = t; i < 1024; i += 256) ((float4*)wsm)[i] = ((const float4*)w)[i];
    __syncthreads();
    unsigned wsm_s = (unsigned)__cvta_generic_to_shared(wsm);

    unsigned long long a[32];
#pragma unroll
    for (int j = 0; j < 32; j++) a[j] = 0ULL;

    for (int c = 0; c < 64; c++) {
        float f = feat[((size_t)b * CC + c) * NP + n];
        unsigned long long f2;
        asm("mov.b64 %0, {%1,%1};" : "=l"(f2) : "f"(f));
        unsigned wrow = wsm_s + (c * 64) * 4;
#pragma unroll
        for (int j = 0; j < 8; j++) {
            unsigned long long w0, w1, w2, w3;
            asm("ld.shared.v2.u64 {%0,%1}, [%2];" : "=l"(w0), "=l"(w1) : "r"(wrow + j * 32));
            asm("ld.shared.v2.u64 {%0,%1}, [%2];" : "=l"(w2), "=l"(w3) : "r"(wrow + j * 32 + 16));
            asm("fma.rn.f32x2 %0, %1, %2, %0;" : "+l"(a[4 * j + 0]) : "l"(w0), "l"(f2));
            asm("fma.rn.f32x2 %0, %1, %2, %0;" : "+l"(a[4 * j + 1]) : "l"(w1), "l"(f2));
            asm("fma.rn.f32x2 %0, %1, %2, %0;" : "+l"(a[4 * j + 2]) : "l"(w2), "l"(f2));
            asm("fma.rn.f32x2 %0, %1, %2, %0;" : "+l"(a[4 * j + 3]) : "l"(w3), "l"(f2));
        }
    }
    float4* o4 = (float4*)&pT[((size_t)b * NP + n) * CC];
#pragma unroll
    for (int j = 0; j < 16; j++) {
        float l0, h0, l1, h1;
        asm("mov.b64 {%0,%1}, %2;" : "=f"(l0), "=f"(h0) : "l"(a[2 * j]));
        asm("mov.b64 {%0,%1}, %2;" : "=f"(l1), "=f"(h1) : "l"(a[2 * j + 1]));
        float4 v;
        v.x = l0 + bias[4 * j + 0];
        v.y = h0 + bias[4 * j + 1];
        v.z = l1 + bias[4 * j + 2];
        v.w = h1 + bias[4 * j + 3];
        o4[j] = v;
    }
}

// ---------------- point-branch BN stats over [b][n][c] ---------------------
__global__ void pstats(const float* __restrict__ pT, float* __restrict__ sum,
                       float* __restrict__ sumsq) {
    int b = blockIdx.y, t = threadIdx.x;
    int c = t & 63, nl = t >> 6;
    int n0 = blockIdx.x * 256;
    float s = 0, q = 0;
    for (int n = n0 + nl; n < n0 + 256; n += 4) {
        float v = pT[((size_t)b * NP + n) * CC + c];
        s += v; q += v * v;
    }
    __shared__ float rs[256], rq[256];
    rs[t] = s; rq[t] = q;
    __syncthreads();
    if (t < 64) {
        s = rs[t] + rs[t + 64] + rs[t + 128] + rs[t + 192];
        q = rq[t] + rq[t + 64] + rq[t + 128] + rq[t + 192];
        atomicAdd(&sum[c], s);
        atomicAdd(&sumsq[c], q);
    }
}

// ---------------- final: devoxelize + BN(p)+lrelu + add, write [b][c][n] ---
__global__ void final_k(const float* __restrict__ vT, const float* __restrict__ pT,
                        const float* __restrict__ normc, const float* __restrict__ sc,
                        const float* __restrict__ sh, float* __restrict__ out) {
    __shared__ float res[64][65];
    __shared__ int cidx[64][8];
    __shared__ float cw[64][8];
    int b = blockIdx.y;
    int n0 = blockIdx.x * 64;
    int t = threadIdx.x;

    if (t < 64) {
        int n = n0 + t;
        float xs = normc[(b * 3 + 0) * NP + n];
        float ys = normc[(b * 3 + 1) * NP + n];
        float zs = normc[(b * 3 + 2) * NP + n];
        float x0f = floorf(xs), y0f = floorf(ys), z0f = floorf(zs);
        float fx = xs - x0f, fy = ys - y0f, fz = zs - z0f;
        int x0 = (int)x0f, y0 = (int)y0f, z0 = (int)z0f;
        int x1 = min(x0 + 1, 31), y1 = min(y0 + 1, 31), z1 = min(z0 + 1, 31);
#pragma unroll
        for (int k = 0; k < 8; k++) {
            int dx = (k >> 2) & 1, dy = (k >> 1) & 1, dz = k & 1;
            float wt = (dx ? fx : 1.0f - fx) * (dy ? fy : 1.0f - fy) * (dz ? fz : 1.0f - fz);
            int idx = ((dx ? x1 : x0) * 32 + (dy ? y1 : y0)) * 32 + (dz ? z1 : z0);
            cidx[t][k] = idx;
            cw[t][k] = wt;
        }
    }
    __syncthreads();

    int c = t & 63, ty = t >> 6;
    float scv = sc[c], shv = sh[c];

    for (int j = ty; j < 64; j += 4) {
        float acc = 0.0f;
#pragma unroll
        for (int k = 0; k < 8; k++)
            acc += cw[j][k] * vT[((size_t)b * NV + cidx[j][k]) * CC + c];
        float pv = fmaf(pT[((size_t)b * NP + n0 + j) * CC + c], scv, shv);
        pv = pv >= 0 ? pv : ALPHA * pv;
        res[c][j] = acc + pv;
    }
    __syncthreads();

    for (int i = t; i < 4096; i += 256) {
        int c2 = i >> 6, j = i & 63;
        out[((size_t)b * CC + c2) * NP + n0 + j] = res[c2][j];
    }
}

// ---------------- launcher ----------------
extern "C" void kernel_launch(void* const* d_in, const int* in_sizes, int n_in,
                              void* d_out, int out_size) {
    const float* feat   = (const float*)d_in[0];
    const float* coords = (const float*)d_in[1];
    const float* c1w    = (const float*)d_in[2];
    const float* c1b    = (const float*)d_in[3];
    const float* g1     = (const float*)d_in[4];
    const float* b1     = (const float*)d_in[5];
    const float* c2w    = (const float*)d_in[6];
    const float* c2b    = (const float*)d_in[7];
    const float* g2     = (const float*)d_in[8];
    const float* b2     = (const float*)d_in[9];
    const float* pw     = (const float*)d_in[10];
    const float* pb     = (const float*)d_in[11];
    const float* pg     = (const float*)d_in[12];
    const float* pbeta  = (const float*)d_in[13];
    float* out = (float*)d_out;

    float *fT, *tmp, *cnt, *bufA, *bufB, *pT, *normc, *cmean, *stats, *scsh;
    unsigned* cmaxb;
    cudaGetSymbolAddress((void**)&fT, g_fT);
    cudaGetSymbolAddress((void**)&tmp, g_tmp);
    cudaGetSymbolAddress((void**)&cnt, g_cnt);
    cudaGetSymbolAddress((void**)&bufA, g_bufA);
    cudaGetSymbolAddress((void**)&bufB, g_bufB);
    cudaGetSymbolAddress((void**)&pT, g_pT);
    cudaGetSymbolAddress((void**)&normc, g_normc);
    cudaGetSymbolAddress((void**)&cmean, g_cmean);
    cudaGetSymbolAddress((void**)&cmaxb, g_cmaxb);
    cudaGetSymbolAddress((void**)&stats, g_stats);
    cudaGetSymbolAddress((void**)&scsh, g_scsh);

    float* sum1 = stats + 0 * CC;  float* sq1 = stats + 1 * CC;
    float* sum2 = stats + 2 * CC;  float* sq2 = stats + 3 * CC;
    float* psum = stats + 4 * CC;  float* psq = stats + 5 * CC;
    float* sc1 = scsh + 0 * CC;    float* sh1 = scsh + 1 * CC;
    float* sc2 = scsh + 2 * CC;    float* sh2 = scsh + 3 * CC;
    float* scp = scsh + 4 * CC;    float* shp = scsh + 5 * CC;

    int dyn = 2 * WBYTES + 2 * PBYTES;  // 96768 B
    cudaFuncSetAttribute(conv3d_v4<false>, cudaFuncAttributeMaxDynamicSharedMemorySize, dyn);
    cudaFuncSetAttribute(conv3d_v4<true>,  cudaFuncAttributeMaxDynamicSharedMemorySize, dyn);

    const float invV = 1.0f / (float)(BB * NV);
    const float invP = 1.0f / (float)(BB * NP);

    // voxelize
    zero_kernel<<<8192, 256>>>(tmp, (size_t)BB * NV * CC);
    zero_kernel<<<256, 256>>>(cnt, (size_t)BB * NV);
    zero_small<<<1, 512>>>(stats, cmean, cmaxb);
    transpose_feat<<<dim3(NP / 32, BB), 256>>>(feat, fT);
    coord_mean_p<<<dim3(32, BB), 256>>>(coords, cmean);
    coord_max_p<<<dim3(32, BB), 256>>>(coords, cmean, cmaxb);
    scatter<<<BB * NP / 4, 256>>>(coords, fT, cmean, cmaxb, normc, tmp, cnt);
    finalize_vox<<<dim3(NV / 32, BB), 256>>>(tmp, cnt, bufA);

    // conv1 (+ fused stats)
    conv3d_v4<false><<<dim3(8, 32, BB), 256, dyn>>>(bufA, bufB, c1w, c1b,
                                                    nullptr, nullptr, sum1, sq1);
    mkscale<<<1, 64>>>(sum1, sq1, g1, b1, invV, sc1, sh1);

    // conv2 (input BN1+lrelu fused into patch load; + fused stats)
    conv3d_v4<true><<<dim3(8, 32, BB), 256, dyn>>>(bufB, bufA, c2w, c2b,
                                                   sc1, sh1, sum2, sq2);
    mkscale<<<1, 64>>>(sum2, sq2, g2, b2, invV, sc2, sh2);

    // BN2 apply + lrelu + transpose to [b][v][c] (reuse tmp as vT)
    bnapply_T<<<dim3(NV / 32, BB), 256>>>(bufA, sc2, sh2, tmp);

    // point branch
    pgemm<<<dim3(NP / 256, BB), 256>>>(feat, pw, pb, pT);
    pstats<<<dim3(NP / 256, BB), 256>>>(pT, psum, psq);
    mkscale<<<1, 64>>>(psum, psq, pg, pbeta, invP, scp, shp);

    // devoxelize + point BN + add
    final_k<<<dim3(NP / 64, BB), 256>>>(tmp, pT, normc, scp, shp, out);

    // coords passthrough (second tuple output), if the harness expects it
    int main_sz = BB * CC * NP;
    int coord_sz = BB * 3 * NP;
    if (out_size >= main_sz + coord_sz)
        copy_kernel<<<coord_sz / 256, 256>>>(coords, out + main_sz, coord_sz);
}

// round 8
// speedup vs baseline: 10.4483x; 2.1850x over previous
#include <cuda_runtime.h>

#define BB 8
#define CC 64
#define NP 16384
#define RR 32
#define NV 32768          // 32^3
#define ALPHA 0.1f
#define BNEPS 1e-4f
#define VOXEPS 1e-6f

// ---------------- scratch (device globals; no allocation allowed) ----------
__device__ float g_fT[BB * NP * CC];        // features transposed [b][n][c]
__device__ float g_tmp[BB * NV * CC];       // voxel sums [b][v][c]; later vT
__device__ float g_cnt[BB * NV];            // voxel counts
__device__ float g_bufA[BB * CC * NV];      // channel-major grid buffers
__device__ float g_bufB[BB * CC * NV];
__device__ float g_pT[BB * NP * CC];        // point branch [b][n][c]
__device__ float g_normc[BB * 3 * NP];      // normalized coords in [0,31]
__device__ float g_cmean[BB * 3];           // coordinate SUMS (divide by NP on use)
__device__ unsigned g_cmaxb[BB];            // max dist^2 as float bits
__device__ float g_stats[6 * CC];           // sum1,sq1,sum2,sq2,psum,psq
__device__ float g_scsh[6 * CC];            // sc1,sh1,sc2,sh2,scp,shp

// ---------------- utility kernels ----------------
__global__ void zero_kernel(float* p, size_t n) {
    size_t i = (size_t)blockIdx.x * blockDim.x + threadIdx.x;
    size_t stride = (size_t)gridDim.x * blockDim.x;
    for (; i < n; i += stride) p[i] = 0.0f;
}

__global__ void zero_small(float* stats, float* cmean, unsigned* cmaxb) {
    int t = threadIdx.x;
    if (t < 6 * CC) stats[t] = 0.0f;
    if (t < BB * 3) cmean[t] = 0.0f;
    if (t < BB) cmaxb[t] = 0u;
}

__global__ void copy_kernel(const float* __restrict__ src, float* __restrict__ dst, int n) {
    int i = blockIdx.x * blockDim.x + threadIdx.x;
    int stride = gridDim.x * blockDim.x;
    for (; i < n; i += stride) dst[i] = src[i];
}

__global__ void mkscale(const float* __restrict__ sum, const float* __restrict__ sumsq,
                        const float* __restrict__ gamma, const float* __restrict__ beta,
                        float invcnt, float* __restrict__ sc, float* __restrict__ sh) {
    int c = threadIdx.x;
    float mean = sum[c] * invcnt;
    float var = sumsq[c] * invcnt - mean * mean;
    float s = gamma[c] * rsqrtf(var + BNEPS);
    sc[c] = s;
    sh[c] = beta[c] - mean * s;
}

// ---------------- features transpose [b][c][n] -> [b][n][c] ----------------
__global__ void transpose_feat(const float* __restrict__ feat, float* __restrict__ fT) {
    __shared__ float s[CC][33];
    int b = blockIdx.y;
    int n0 = blockIdx.x * 32;
    int t = threadIdx.x;
    for (int i = t; i < 32 * 64; i += 256) {
        int c = i >> 5, n = i & 31;
        s[c][n] = feat[(b * CC + c) * NP + n0 + n];
    }
    __syncthreads();
    for (int i = t; i < 32 * 64; i += 256) {
        int n = i >> 6, c = i & 63;
        fT[((size_t)b * NP + n0 + n) * CC + c] = s[c][n];
    }
}

// ---------------- coord statistics ----------------
__global__ void coord_mean_p(const float* __restrict__ coords, float* __restrict__ cmean) {
    int b = blockIdx.y;
    int n0 = blockIdx.x * 512;
    int t = threadIdx.x;
    float s0 = 0, s1 = 0, s2 = 0;
    for (int n = n0 + t; n < n0 + 512; n += 256) {
        s0 += coords[(b * 3 + 0) * NP + n];
        s1 += coords[(b * 3 + 1) * NP + n];
        s2 += coords[(b * 3 + 2) * NP + n];
    }
#pragma unroll
    for (int o = 16; o > 0; o >>= 1) {
        s0 += __shfl_xor_sync(0xffffffff, s0, o);
        s1 += __shfl_xor_sync(0xffffffff, s1, o);
        s2 += __shfl_xor_sync(0xffffffff, s2, o);
    }
    if ((t & 31) == 0) {
        atomicAdd(&cmean[b * 3 + 0], s0);
        atomicAdd(&cmean[b * 3 + 1], s1);
        atomicAdd(&cmean[b * 3 + 2], s2);
    }
}

__global__ void coord_max_p(const float* __restrict__ coords, const float* __restrict__ cmean,
                            unsigned* __restrict__ cmaxb) {
    int b = blockIdx.y;
    int n0 = blockIdx.x * 512;
    int t = threadIdx.x;
    float invn = 1.0f / (float)NP;
    float mx = cmean[b * 3 + 0] * invn, my = cmean[b * 3 + 1] * invn, mz = cmean[b * 3 + 2] * invn;
    float m = 0.0f;
    for (int n = n0 + t; n < n0 + 512; n += 256) {
        float dx = coords[(b * 3 + 0) * NP + n] - mx;
        float dy = coords[(b * 3 + 1) * NP + n] - my;
        float dz = coords[(b * 3 + 2) * NP + n] - mz;
        m = fmaxf(m, dx * dx + dy * dy + dz * dz);
    }
#pragma unroll
    for (int o = 16; o > 0; o >>= 1) m = fmaxf(m, __shfl_xor_sync(0xffffffff, m, o));
    if ((t & 31) == 0) atomicMax(&cmaxb[b], __float_as_uint(m));
}

// ---------------- voxelize scatter ----------------
__global__ void scatter(const float* __restrict__ coords, const float* __restrict__ fT,
                        const float* __restrict__ cmean, const unsigned* __restrict__ cmaxb,
                        float* __restrict__ normc, float* __restrict__ tmp,
                        float* __restrict__ cnt) {
    int t = threadIdx.x;
    int pi = blockIdx.x * 4 + (t >> 6);
    int c = t & 63;
    int b = pi / NP;
    int n = pi - b * NP;

    float invn = 1.0f / (float)NP;
    float r = sqrtf(__uint_as_float(cmaxb[b]));
    float inv = 1.0f / (2.0f * r + VOXEPS);
    float nx = (coords[(b * 3 + 0) * NP + n] - cmean[b * 3 + 0] * invn) * inv + 0.5f;
    float ny = (coords[(b * 3 + 1) * NP + n] - cmean[b * 3 + 1] * invn) * inv + 0.5f;
    float nz = (coords[(b * 3 + 2) * NP + n] - cmean[b * 3 + 2] * invn) * inv + 0.5f;
    nx = fminf(fmaxf(nx * (float)RR, 0.0f), (float)(RR - 1));
    ny = fminf(fmaxf(ny * (float)RR, 0.0f), (float)(RR - 1));
    nz = fminf(fmaxf(nz * (float)RR, 0.0f), (float)(RR - 1));
    int vx = __float2int_rn(nx), vy = __float2int_rn(ny), vz = __float2int_rn(nz);
    int v = (vx * RR + vy) * RR + vz;

    float f = fT[((size_t)b * NP + n) * CC + c];
    atomicAdd(&tmp[((size_t)b * NV + v) * CC + c], f);
    if (c == 0) atomicAdd(&cnt[b * NV + v], 1.0f);
    if (c < 3) normc[(b * 3 + c) * NP + n] = (c == 0 ? nx : (c == 1 ? ny : nz));
}

// ---------------- finalize: [b][v][c]/count -> [b][c][v] -------------------
__global__ void finalize_vox(const float* __restrict__ tmp, const float* __restrict__ cnt,
                             float* __restrict__ grid) {
    __shared__ float s[CC][33];
    __shared__ float cs[32];
    int b = blockIdx.y;
    int v0 = blockIdx.x * 32;
    int t = threadIdx.x;
    for (int i = t; i < 32 * 64; i += 256) {
        int v = i >> 6, c = i & 63;
        s[c][v] = tmp[((size_t)b * NV + v0 + v) * CC + c];
    }
    if (t < 32) cs[t] = fmaxf(cnt[b * NV + v0 + t], 1.0f);
    __syncthreads();
    for (int i = t; i < 32 * 64; i += 256) {
        int c = i >> 5, v = i & 31;
        grid[((size_t)b * CC + c) * NV + v0 + v] = s[c][v] / cs[v];
    }
}

// ================= tf32 mma.sync conv (baseline PTX, sm_80+) ===============
// CTA: M=128 spatial (4y x 32x) x N=64 cout, fixed (z,b). 8 warps, each 32x32.
// K = 2 ci-groups x 27 koffs x 32 ci; per (cig,koff): 4 K8-steps, 8 MMA each.
// A: direct from channels-last slab (pitch 36 words, conflict-free frags).
// B: W[koff][ci][cout] staged per koff into wsm (pitch 72, conflict-free),
//    double-buffered with register prefetch. Epilogue: smem bounce + stats.

static __device__ __forceinline__ float tf32_rna(float v) {
    unsigned u;
    asm("cvt.rna.tf32.f32 %0, %1;" : "=r"(u) : "f"(v));
    return __uint_as_float(u);
}

#define LDS32(dst, addr) asm volatile("ld.shared.b32 %0, [%1];" : "=r"(dst) : "r"(addr))
#define MMA_TF32(d, a0, a1, a2, a3, b0, b1)                                   \
    asm volatile(                                                             \
        "mma.sync.aligned.m16n8k8.row.col.f32.tf32.tf32.f32 "                 \
        "{%0,%1,%2,%3}, {%4,%5,%6,%7}, {%8,%9}, {%0,%1,%2,%3};"               \
        : "+f"(d[0]), "+f"(d[1]), "+f"(d[2]), "+f"(d[3])                      \
        : "r"(a0), "r"(a1), "r"(a2), "r"(a3), "r"(b0), "r"(b1))

#define WSM_FLOATS 2304   // 32 ci x 72 pitch
#define SLAB_FLOATS 22032 // (3z*6y)*34x rows x 36 pitch
#define CONV_DYN ((2 * WSM_FLOATS + SLAB_FLOATS) * 4)  // 106560 B

template <bool APPLY>
__global__ __launch_bounds__(256, 2)
void conv3d_mma(const float* __restrict__ in, float* __restrict__ out,
                const float* __restrict__ w, const float* __restrict__ bias,
                const float* __restrict__ insc, const float* __restrict__ insh,
                float* __restrict__ gsum, float* __restrict__ gsumsq) {
    extern __shared__ __align__(16) float dsm[];
    __shared__ float sc_sm[64], sh_sm[64], bias_sm[64];

    float* wsm0 = dsm;
    float* wsm1 = dsm + WSM_FLOATS;
    float* slab = dsm + 2 * WSM_FLOATS;
    float* res = slab;  // reused after compute

    int b = blockIdx.z, z0 = blockIdx.y, y0 = blockIdx.x * 4;
    int t = threadIdx.x, lane = t & 31, wid = t >> 5;
    int wy = wid >> 1, wn = wid & 1;            // warp: y-row 0..3, n-half 0..1
    int gid = lane >> 2, tig = lane & 3;        // mma fragment coords

    unsigned slab_s = (unsigned)__cvta_generic_to_shared(slab);
    unsigned wsm_s[2] = {(unsigned)__cvta_generic_to_shared(wsm0),
                         (unsigned)__cvta_generic_to_shared(wsm1)};

    if (t < 64) {
        bias_sm[t] = bias[t];
        if (APPLY) { sc_sm[t] = insc[t]; sh_sm[t] = insh[t]; }
    }
    __syncthreads();

    const float* inb = in + (size_t)b * CC * NV;

    float acc[2][4][4];
#pragma unroll
    for (int mt = 0; mt < 2; mt++)
#pragma unroll
        for (int nt = 0; nt < 4; nt++)
#pragma unroll
            for (int e = 0; e < 4; e++) acc[mt][nt][e] = 0.0f;

    // channels-last slab: row (zs*6+ys)*34+xs, 32 channels, pitch 36 floats
    auto load_slab = [&](int cig) {
        for (int i = t; i < 4896; i += 256) {
            int zy = i / 272, r = i - zy * 272;   // 272 = 8 c4 * 34 xs
            int c4 = r / 34, xs = r - c4 * 34;
            int zs = zy / 6, ys = zy - zs * 6;
            int zg = z0 - 1 + zs, yg = y0 - 1 + ys, xg = xs - 1;
            bool ok = (unsigned)zg < 32u && (unsigned)yg < 32u && (unsigned)xg < 32u;
            int vox = zg * 1024 + yg * 32 + xg;
            float4 val;
            float* vp = &val.x;
#pragma unroll
            for (int j = 0; j < 4; j++) {
                int c = cig * 32 + c4 * 4 + j;
                float v = ok ? __ldg(inb + (size_t)c * NV + vox) : 0.0f;
                if (APPLY) {
                    float u = fmaf(v, sc_sm[c], sh_sm[c]);
                    v = u >= 0 ? u : ALPHA * u;
                    if (!ok) v = 0.0f;
                }
                vp[j] = tf32_rna(v);
            }
            *(float4*)(slab + (size_t)((zs * 6 + ys) * 34 + xs) * 36 + c4 * 4) = val;
        }
    };

    float4 wr0, wr1;
    auto w_prefetch = [&](int cig, int koff) {
        const float4* wg = (const float4*)(w + (size_t)(koff * 64 + cig * 32) * 64);
        wr0 = __ldg(&wg[t]);
        wr1 = __ldg(&wg[t + 256]);
    };
    auto w_sts = [&](float* dst) {
#pragma unroll
        for (int k = 0; k < 2; k++) {
            float4 v = k ? wr1 : wr0;
            int e = (t + k * 256) * 4;            // element in [ci*64+co]
            float* d = dst + (e >> 6) * 72 + (e & 63);
            d[0] = tf32_rna(v.x); d[1] = tf32_rna(v.y);
            d[2] = tf32_rna(v.z); d[3] = tf32_rna(v.w);
        }
    };

    auto compute = [&](int buf, int koff) {
        int dz = koff / 9, rem = koff - dz * 9;
        int dy = rem / 3, dx = rem - dy * 3;
        unsigned a_base = slab_s +
            (unsigned)((((dz * 6 + wy + dy) * 34) + gid + dx) * 36 + tig) * 4;
        unsigned b_base = wsm_s[buf] + (unsigned)(tig * 72 + wn * 32 + gid) * 4;
#pragma unroll
        for (int ks = 0; ks < 4; ks++) {
            unsigned ab = a_base + ks * 32;       // +8 ci
            unsigned bb = b_base + ks * 2304;     // +8 ci rows (8*72*4)
            unsigned a0, a1, a2, a3, a4, a5, a6, a7;
            LDS32(a0, ab);            LDS32(a1, ab + 1152);          // +8 rows
            LDS32(a2, ab + 16);       LDS32(a3, ab + 1168);          // ci+4
            LDS32(a4, ab + 2304);     LDS32(a5, ab + 3456);          // mtile1 (+16 rows)
            LDS32(a6, ab + 2320);     LDS32(a7, ab + 3472);
            unsigned b0[4], b1[4];
#pragma unroll
            for (int nt = 0; nt < 4; nt++) {
                LDS32(b0[nt], bb + nt * 32);
                LDS32(b1[nt], bb + nt * 32 + 1152);                  // ci+4 (4*72*4)
            }
#pragma unroll
            for (int nt = 0; nt < 4; nt++) {
                MMA_TF32(acc[0][nt], a0, a1, a2, a3, b0[nt], b1[nt]);
                MMA_TF32(acc[1][nt], a4, a5, a6, a7, b0[nt], b1[nt]);
            }
        }
    };

    // ---- main loops ----
#pragma unroll 1
    for (int cig = 0; cig < 2; cig++) {
        load_slab(cig);
        w_prefetch(cig, 0);
        w_sts(wsm0);
        __syncthreads();
#pragma unroll 1
        for (int koff = 0; koff < 27; koff++) {
            if (koff < 26) w_prefetch(cig, koff + 1);
            compute(koff & 1, koff);
            if (koff < 26) w_sts((koff & 1) ? wsm0 : wsm1);
            __syncthreads();
        }
    }

    // ---- epilogue: bounce D to smem, coalesced store + fused BN stats ----
    // res layout: [spat 128][cout pitch 66]
#pragma unroll
    for (int mt = 0; mt < 2; mt++)
#pragma unroll
        for (int nt = 0; nt < 4; nt++) {
            int spat0 = wy * 32 + mt * 16 + gid;
            int cout0 = wn * 32 + nt * 8 + tig * 2;
            *(float2*)(res + spat0 * 66 + cout0) =
                make_float2(acc[mt][nt][0], acc[mt][nt][1]);
            *(float2*)(res + (spat0 + 8) * 66 + cout0) =
                make_float2(acc[mt][nt][2], acc[mt][nt][3]);
        }
    __syncthreads();

    size_t obase = (size_t)b * CC * NV + (size_t)z0 * 1024 + (size_t)y0 * 32;
#pragma unroll
    for (int j = 0; j < 8; j++) {
        int c = wid * 8 + j;
        float bval = bias_sm[c];
        float s = 0, q = 0;
#pragma unroll
        for (int sy = 0; sy < 4; sy++) {
            float v = res[(sy * 32 + lane) * 66 + c] + bval;
            out[obase + (size_t)c * NV + sy * 32 + lane] = v;
            s += v; q += v * v;
        }
#pragma unroll
        for (int o = 16; o > 0; o >>= 1) {
            s += __shfl_xor_sync(0xffffffff, s, o);
            q += __shfl_xor_sync(0xffffffff, q, o);
        }
        if (lane == 0) {
            atomicAdd(&gsum[c], s);
            atomicAdd(&gsumsq[c], q);
        }
    }
}

// ---------------- BN apply + LeakyReLU + transpose to [b][v][c] ------------
__global__ void bnapply_T(const float* __restrict__ x, const float* __restrict__ sc,
                          const float* __restrict__ sh, float* __restrict__ vT) {
    __shared__ float s[CC][33];
    int b = blockIdx.y;
    int v0 = blockIdx.x * 32;
    int t = threadIdx.x;
    for (int i = t; i < 32 * 64; i += 256) {
        int c = i >> 5, v = i & 31;
        float u = fmaf(x[((size_t)b * CC + c) * NV + v0 + v], sc[c], sh[c]);
        s[c][v] = u >= 0 ? u : ALPHA * u;
    }
    __syncthreads();
    for (int i = t; i < 32 * 64; i += 256) {
        int v = i >> 6, c = i & 63;
        vT[((size_t)b * NV + v0 + v) * CC + c] = s[c][v];
    }
}

// ---------------- point branch GEMM (FFMA2) --------------------------------
__global__ void pgemm(const float* __restrict__ feat, const float* __restrict__ w,
                      const float* __restrict__ bias, float* __restrict__ pT) {
    __shared__ __align__(16) float wsm[64 * 64];
    int b = blockIdx.y;
    int n = blockIdx.x * 256 + threadIdx.x;
    int t = threadIdx.x;
    for (int i = t; i < 1024; i += 256) ((float4*)wsm)[i] = ((const float4*)w)[i];
    __syncthreads();
    unsigned wsm_s = (unsigned)__cvta_generic_to_shared(wsm);

    unsigned long long a[32];
#pragma unroll
    for (int j = 0; j < 32; j++) a[j] = 0ULL;

    for (int c = 0; c < 64; c++) {
        float f = feat[((size_t)b * CC + c) * NP + n];
        unsigned long long f2;
        asm("mov.b64 %0, {%1,%1};" : "=l"(f2) : "f"(f));
        unsigned wrow = wsm_s + (c * 64) * 4;
#pragma unroll
        for (int j = 0; j < 8; j++) {
            unsigned long long w0, w1, w2, w3;
            asm("ld.shared.v2.u64 {%0,%1}, [%2];" : "=l"(w0), "=l"(w1) : "r"(wrow + j * 32));
            asm("ld.shared.v2.u64 {%0,%1}, [%2];" : "=l"(w2), "=l"(w3) : "r"(wrow + j * 32 + 16));
            asm("fma.rn.f32x2 %0, %1, %2, %0;" : "+l"(a[4 * j + 0]) : "l"(w0), "l"(f2));
            asm("fma.rn.f32x2 %0, %1, %2, %0;" : "+l"(a[4 * j + 1]) : "l"(w1), "l"(f2));
            asm("fma.rn.f32x2 %0, %1, %2, %0;" : "+l"(a[4 * j + 2]) : "l"(w2), "l"(f2));
            asm("fma.rn.f32x2 %0, %1, %2, %0;" : "+l"(a[4 * j + 3]) : "l"(w3), "l"(f2));
        }
    }
    float4* o4 = (float4*)&pT[((size_t)b * NP + n) * CC];
#pragma unroll
    for (int j = 0; j < 16; j++) {
        float l0, h0, l1, h1;
        asm("mov.b64 {%0,%1}, %2;" : "=f"(l0), "=f"(h0) : "l"(a[2 * j]));
        asm("mov.b64 {%0,%1}, %2;" : "=f"(l1), "=f"(h1) : "l"(a[2 * j + 1]));
        float4 v;
        v.x = l0 + bias[4 * j + 0];
        v.y = h0 + bias[4 * j + 1];
        v.z = l1 + bias[4 * j + 2];
        v.w = h1 + bias[4 * j + 3];
        o4[j] = v;
    }
}

// ---------------- point-branch BN stats ------------------------------------
__global__ void pstats(const float* __restrict__ pT, float* __restrict__ sum,
                       float* __restrict__ sumsq) {
    int b = blockIdx.y, t = threadIdx.x;
    int c = t & 63, nl = t >> 6;
    int n0 = blockIdx.x * 256;
    float s = 0, q = 0;
    for (int n = n0 + nl; n < n0 + 256; n += 4) {
        float v = pT[((size_t)b * NP + n) * CC + c];
        s += v; q += v * v;
    }
    __shared__ float rs[256], rq[256];
    rs[t] = s; rq[t] = q;
    __syncthreads();
    if (t < 64) {
        s = rs[t] + rs[t + 64] + rs[t + 128] + rs[t + 192];
        q = rq[t] + rq[t + 64] + rq[t + 128] + rq[t + 192];
        atomicAdd(&sum[c], s);
        atomicAdd(&sumsq[c], q);
    }
}

// ---------------- final: devoxelize + BN(p)+lrelu + add --------------------
__global__ void final_k(const float* __restrict__ vT, const float* __restrict__ pT,
                        const float* __restrict__ normc, const float* __restrict__ sc,
                        const float* __restrict__ sh, float* __restrict__ out) {
    __shared__ float res[64][65];
    __shared__ int cidx[64][8];
    __shared__ float cw[64][8];
    int b = blockIdx.y;
    int n0 = blockIdx.x * 64;
    int t = threadIdx.x;

    if (t < 64) {
        int n = n0 + t;
        float xs = normc[(b * 3 + 0) * NP + n];
        float ys = normc[(b * 3 + 1) * NP + n];
        float zs = normc[(b * 3 + 2) * NP + n];
        float x0f = floorf(xs), y0f = floorf(ys), z0f = floorf(zs);
        float fx = xs - x0f, fy = ys - y0f, fz = zs - z0f;
        int x0 = (int)x0f, y0 = (int)y0f, z0 = (int)z0f;
        int x1 = min(x0 + 1, 31), y1 = min(y0 + 1, 31), z1 = min(z0 + 1, 31);
#pragma unroll
        for (int k = 0; k < 8; k++) {
            int dx = (k >> 2) & 1, dy = (k >> 1) & 1, dz = k & 1;
            float wt = (dx ? fx : 1.0f - fx) * (dy ? fy : 1.0f - fy) * (dz ? fz : 1.0f - fz);
            int idx = ((dx ? x1 : x0) * 32 + (dy ? y1 : y0)) * 32 + (dz ? z1 : z0);
            cidx[t][k] = idx;
            cw[t][k] = wt;
        }
    }
    __syncthreads();

    int c = t & 63, ty = t >> 6;
    float scv = sc[c], shv = sh[c];

    for (int j = ty; j < 64; j += 4) {
        float acc = 0.0f;
#pragma unroll
        for (int k = 0; k < 8; k++)
            acc += cw[j][k] * vT[((size_t)b * NV + cidx[j][k]) * CC + c];
        float pv = fmaf(pT[((size_t)b * NP + n0 + j) * CC + c], scv, shv);
        pv = pv >= 0 ? pv : ALPHA * pv;
        res[c][j] = acc + pv;
    }
    __syncthreads();

    for (int i = t; i < 4096; i += 256) {
        int c2 = i >> 6, j = i & 63;
        out[((size_t)b * CC + c2) * NP + n0 + j] = res[c2][j];
    }
}

// ---------------- launcher ----------------
extern "C" void kernel_launch(void* const* d_in, const int* in_sizes, int n_in,
                              void* d_out, int out_size) {
    const float* feat   = (const float*)d_in[0];
    const float* coords = (const float*)d_in[1];
    const float* c1w    = (const float*)d_in[2];
    const float* c1b    = (const float*)d_in[3];
    const float* g1     = (const float*)d_in[4];
    const float* b1     = (const float*)d_in[5];
    const float* c2w    = (const float*)d_in[6];
    const float* c2b    = (const float*)d_in[7];
    const float* g2     = (const float*)d_in[8];
    const float* b2     = (const float*)d_in[9];
    const float* pw     = (const float*)d_in[10];
    const float* pb     = (const float*)d_in[11];
    const float* pg     = (const float*)d_in[12];
    const float* pbeta  = (const float*)d_in[13];
    float* out = (float*)d_out;

    float *fT, *tmp, *cnt, *bufA, *bufB, *pT, *normc, *cmean, *stats, *scsh;
    unsigned* cmaxb;
    cudaGetSymbolAddress((void**)&fT, g_fT);
    cudaGetSymbolAddress((void**)&tmp, g_tmp);
    cudaGetSymbolAddress((void**)&cnt, g_cnt);
    cudaGetSymbolAddress((void**)&bufA, g_bufA);
    cudaGetSymbolAddress((void**)&bufB, g_bufB);
    cudaGetSymbolAddress((void**)&pT, g_pT);
    cudaGetSymbolAddress((void**)&normc, g_normc);
    cudaGetSymbolAddress((void**)&cmean, g_cmean);
    cudaGetSymbolAddress((void**)&cmaxb, g_cmaxb);
    cudaGetSymbolAddress((void**)&stats, g_stats);
    cudaGetSymbolAddress((void**)&scsh, g_scsh);

    float* sum1 = stats + 0 * CC;  float* sq1 = stats + 1 * CC;
    float* sum2 = stats + 2 * CC;  float* sq2 = stats + 3 * CC;
    float* psum = stats + 4 * CC;  float* psq = stats + 5 * CC;
    float* sc1 = scsh + 0 * CC;    float* sh1 = scsh + 1 * CC;
    float* sc2 = scsh + 2 * CC;    float* sh2 = scsh + 3 * CC;
    float* scp = scsh + 4 * CC;    float* shp = scsh + 5 * CC;

    cudaFuncSetAttribute(conv3d_mma<false>, cudaFuncAttributeMaxDynamicSharedMemorySize, CONV_DYN);
    cudaFuncSetAttribute(conv3d_mma<true>,  cudaFuncAttributeMaxDynamicSharedMemorySize, CONV_DYN);

    const float invV = 1.0f / (float)(BB * NV);
    const float invP = 1.0f / (float)(BB * NP);

    // voxelize
    zero_kernel<<<8192, 256>>>(tmp, (size_t)BB * NV * CC);
    zero_kernel<<<256, 256>>>(cnt, (size_t)BB * NV);
    zero_small<<<1, 512>>>(stats, cmean, cmaxb);
    transpose_feat<<<dim3(NP / 32, BB), 256>>>(feat, fT);
    coord_mean_p<<<dim3(32, BB), 256>>>(coords, cmean);
    coord_max_p<<<dim3(32, BB), 256>>>(coords, cmean, cmaxb);
    scatter<<<BB * NP / 4, 256>>>(coords, fT, cmean, cmaxb, normc, tmp, cnt);
    finalize_vox<<<dim3(NV / 32, BB), 256>>>(tmp, cnt, bufA);

    // conv1 (tf32 mma.sync tensor cores, + fused stats)
    conv3d_mma<false><<<dim3(8, 32, BB), 256, CONV_DYN>>>(bufA, bufB, c1w, c1b,
                                                          nullptr, nullptr, sum1, sq1);
    mkscale<<<1, 64>>>(sum1, sq1, g1, b1, invV, sc1, sh1);

    // conv2 (input BN1+lrelu fused into slab load; + fused stats)
    conv3d_mma<true><<<dim3(8, 32, BB), 256, CONV_DYN>>>(bufB, bufA, c2w, c2b,
                                                         sc1, sh1, sum2, sq2);
    mkscale<<<1, 64>>>(sum2, sq2, g2, b2, invV, sc2, sh2);

    // BN2 apply + lrelu + transpose to [b][v][c] (reuse tmp as vT)
    bnapply_T<<<dim3(NV / 32, BB), 256>>>(bufA, sc2, sh2, tmp);

    // point branch
    pgemm<<<dim3(NP / 256, BB), 256>>>(feat, pw, pb, pT);
    pstats<<<dim3(NP / 256, BB), 256>>>(pT, psum, psq);
    mkscale<<<1, 64>>>(psum, psq, pg, pbeta, invP, scp, shp);

    // devoxelize + point BN + add
    final_k<<<dim3(NP / 64, BB), 256>>>(tmp, pT, normc, scp, shp, out);

    // coords passthrough (second tuple output), if the harness expects it
    int main_sz = BB * CC * NP;
    int coord_sz = BB * 3 * NP;
    if (out_size >= main_sz + coord_sz)
        copy_kernel<<<coord_sz / 256, 256>>>(coords, out + main_sz, coord_sz);
}

// round 9
// speedup vs baseline: 10.9648x; 1.0494x over previous
#include <cuda_runtime.h>

#define BB 8
#define CC 64
#define NP 16384
#define RR 32
#define NV 32768          // 32^3
#define ALPHA 0.1f
#define BNEPS 1e-4f
#define VOXEPS 1e-6f

// ---------------- scratch (device globals; no allocation allowed) ----------
__device__ float g_fT[BB * NP * CC];        // features transposed [b][n][c]
__device__ float g_tmp[BB * NV * CC];       // voxel sums [b][v][c]; later raw conv2 out (channels-last)
__device__ float g_cnt[BB * NV];            // voxel counts
__device__ float g_bufB[BB * CC * NV];      // conv1 output (channel-major)
__device__ float g_pT[BB * NP * CC];        // point branch [b][n][c]
__device__ float g_normc[BB * 3 * NP];      // normalized coords in [0,31]
__device__ float g_cmean[BB * 3];           // coordinate SUMS
__device__ unsigned g_cmaxb[BB];            // max dist^2 as float bits
__device__ float g_stats[6 * CC];           // sum1,sq1,sum2,sq2,psum,psq
__device__ float g_scsh[6 * CC];            // sc1,sh1,sc2,sh2,scp,shp

// ---------------- utility kernels ----------------
__global__ void zero_kernel(float* p, size_t n) {
    size_t i = (size_t)blockIdx.x * blockDim.x + threadIdx.x;
    size_t stride = (size_t)gridDim.x * blockDim.x;
    for (; i < n; i += stride) p[i] = 0.0f;
}

__global__ void zero_small(float* stats, float* cmean, unsigned* cmaxb) {
    int t = threadIdx.x;
    if (t < 6 * CC) stats[t] = 0.0f;
    if (t < BB * 3) cmean[t] = 0.0f;
    if (t < BB) cmaxb[t] = 0u;
}

__global__ void copy_kernel(const float* __restrict__ src, float* __restrict__ dst, int n) {
    int i = blockIdx.x * blockDim.x + threadIdx.x;
    int stride = gridDim.x * blockDim.x;
    for (; i < n; i += stride) dst[i] = src[i];
}

__global__ void mkscale(const float* __restrict__ sum, const float* __restrict__ sumsq,
                        const float* __restrict__ gamma, const float* __restrict__ beta,
                        float invcnt, float* __restrict__ sc, float* __restrict__ sh) {
    int c = threadIdx.x;
    float mean = sum[c] * invcnt;
    float var = sumsq[c] * invcnt - mean * mean;
    float s = gamma[c] * rsqrtf(var + BNEPS);
    sc[c] = s;
    sh[c] = beta[c] - mean * s;
}

// ---------------- features transpose [b][c][n] -> [b][n][c] ----------------
__global__ void transpose_feat(const float* __restrict__ feat, float* __restrict__ fT) {
    __shared__ float s[CC][33];
    int b = blockIdx.y;
    int n0 = blockIdx.x * 32;
    int t = threadIdx.x;
    for (int i = t; i < 32 * 64; i += 256) {
        int c = i >> 5, n = i & 31;
        s[c][n] = feat[(b * CC + c) * NP + n0 + n];
    }
    __syncthreads();
    for (int i = t; i < 32 * 64; i += 256) {
        int n = i >> 6, c = i & 63;
        fT[((size_t)b * NP + n0 + n) * CC + c] = s[c][n];
    }
}

// ---------------- coord statistics ----------------
__global__ void coord_mean_p(const float* __restrict__ coords, float* __restrict__ cmean) {
    int b = blockIdx.y;
    int n0 = blockIdx.x * 512;
    int t = threadIdx.x;
    float s0 = 0, s1 = 0, s2 = 0;
    for (int n = n0 + t; n < n0 + 512; n += 256) {
        s0 += coords[(b * 3 + 0) * NP + n];
        s1 += coords[(b * 3 + 1) * NP + n];
        s2 += coords[(b * 3 + 2) * NP + n];
    }
#pragma unroll
    for (int o = 16; o > 0; o >>= 1) {
        s0 += __shfl_xor_sync(0xffffffff, s0, o);
        s1 += __shfl_xor_sync(0xffffffff, s1, o);
        s2 += __shfl_xor_sync(0xffffffff, s2, o);
    }
    if ((t & 31) == 0) {
        atomicAdd(&cmean[b * 3 + 0], s0);
        atomicAdd(&cmean[b * 3 + 1], s1);
        atomicAdd(&cmean[b * 3 + 2], s2);
    }
}

__global__ void coord_max_p(const float* __restrict__ coords, const float* __restrict__ cmean,
                            unsigned* __restrict__ cmaxb) {
    int b = blockIdx.y;
    int n0 = blockIdx.x * 512;
    int t = threadIdx.x;
    float invn = 1.0f / (float)NP;
    float mx = cmean[b * 3 + 0] * invn, my = cmean[b * 3 + 1] * invn, mz = cmean[b * 3 + 2] * invn;
    float m = 0.0f;
    for (int n = n0 + t; n < n0 + 512; n += 256) {
        float dx = coords[(b * 3 + 0) * NP + n] - mx;
        float dy = coords[(b * 3 + 1) * NP + n] - my;
        float dz = coords[(b * 3 + 2) * NP + n] - mz;
        m = fmaxf(m, dx * dx + dy * dy + dz * dz);
    }
#pragma unroll
    for (int o = 16; o > 0; o >>= 1) m = fmaxf(m, __shfl_xor_sync(0xffffffff, m, o));
    if ((t & 31) == 0) atomicMax(&cmaxb[b], __float_as_uint(m));
}

// ---------------- voxelize scatter ----------------
__global__ void scatter(const float* __restrict__ coords, const float* __restrict__ fT,
                        const float* __restrict__ cmean, const unsigned* __restrict__ cmaxb,
                        float* __restrict__ normc, float* __restrict__ tmp,
                        float* __restrict__ cnt) {
    int t = threadIdx.x;
    int pi = blockIdx.x * 4 + (t >> 6);
    int c = t & 63;
    int b = pi / NP;
    int n = pi - b * NP;

    float invn = 1.0f / (float)NP;
    float r = sqrtf(__uint_as_float(cmaxb[b]));
    float inv = 1.0f / (2.0f * r + VOXEPS);
    float nx = (coords[(b * 3 + 0) * NP + n] - cmean[b * 3 + 0] * invn) * inv + 0.5f;
    float ny = (coords[(b * 3 + 1) * NP + n] - cmean[b * 3 + 1] * invn) * inv + 0.5f;
    float nz = (coords[(b * 3 + 2) * NP + n] - cmean[b * 3 + 2] * invn) * inv + 0.5f;
    nx = fminf(fmaxf(nx * (float)RR, 0.0f), (float)(RR - 1));
    ny = fminf(fmaxf(ny * (float)RR, 0.0f), (float)(RR - 1));
    nz = fminf(fmaxf(nz * (float)RR, 0.0f), (float)(RR - 1));
    int vx = __float2int_rn(nx), vy = __float2int_rn(ny), vz = __float2int_rn(nz);
    int v = (vx * RR + vy) * RR + vz;

    float f = fT[((size_t)b * NP + n) * CC + c];
    atomicAdd(&tmp[((size_t)b * NV + v) * CC + c], f);
    if (c == 0) atomicAdd(&cnt[b * NV + v], 1.0f);
    if (c < 3) normc[(b * 3 + c) * NP + n] = (c == 0 ? nx : (c == 1 ? ny : nz));
}

// ================= tf32 mma.sync conv =======================================
// CTA: M=128 spatial (4y x 32x) x N=64 cout, fixed (z,b). 8 warps, each 32x32.
// INMODE 0: input = voxel sums [b][v][c] / max(cnt,1)  (fuses finalize_vox)
// INMODE 1: input = channel-major buf with BN+lrelu applied at load
// OUTMODE 0: channel-major [b][c][v] out;  OUTMODE 1: channels-last [b][v][c]

static __device__ __forceinline__ float tf32_rna(float v) {
    unsigned u;
    asm("cvt.rna.tf32.f32 %0, %1;" : "=r"(u) : "f"(v));
    return __uint_as_float(u);
}

#define LDS32(dst, addr) asm volatile("ld.shared.b32 %0, [%1];" : "=r"(dst) : "r"(addr))
#define MMA_TF32(d, a0, a1, a2, a3, b0, b1)                                   \
    asm volatile(                                                             \
        "mma.sync.aligned.m16n8k8.row.col.f32.tf32.tf32.f32 "                 \
        "{%0,%1,%2,%3}, {%4,%5,%6,%7}, {%8,%9}, {%0,%1,%2,%3};"               \
        : "+f"(d[0]), "+f"(d[1]), "+f"(d[2]), "+f"(d[3])                      \
        : "r"(a0), "r"(a1), "r"(a2), "r"(a3), "r"(b0), "r"(b1))

#define WSM_FLOATS 2304   // 32 ci x 72 pitch
#define SLAB_FLOATS 22032 // (3z*6y)*34x rows x 36 pitch
#define RES_PITCH 68
#define CONV_DYN ((2 * WSM_FLOATS + SLAB_FLOATS) * 4)  // 106560 B

template <int INMODE, int OUTMODE>
__global__ __launch_bounds__(256, 2)
void conv3d_mma(const float* __restrict__ in, const float* __restrict__ cnt,
                float* __restrict__ out,
                const float* __restrict__ w, const float* __restrict__ bias,
                const float* __restrict__ insc, const float* __restrict__ insh,
                float* __restrict__ gsum, float* __restrict__ gsumsq) {
    extern __shared__ __align__(16) float dsm[];
    __shared__ float sc_sm[64], sh_sm[64], bias_sm[64];

    float* wsm0 = dsm;
    float* wsm1 = dsm + WSM_FLOATS;
    float* slab = dsm + 2 * WSM_FLOATS;
    float* res = slab;  // reused after compute (128 x RES_PITCH <= SLAB_FLOATS)

    int b = blockIdx.z, z0 = blockIdx.y, y0 = blockIdx.x * 4;
    int t = threadIdx.x, lane = t & 31, wid = t >> 5;
    int wy = wid >> 1, wn = wid & 1;
    int gid = lane >> 2, tig = lane & 3;

    unsigned slab_s = (unsigned)__cvta_generic_to_shared(slab);
    unsigned wsm_s[2] = {(unsigned)__cvta_generic_to_shared(wsm0),
                         (unsigned)__cvta_generic_to_shared(wsm1)};

    if (t < 64) {
        bias_sm[t] = bias[t];
        if (INMODE == 1) { sc_sm[t] = insc[t]; sh_sm[t] = insh[t]; }
    }
    __syncthreads();

    float acc[2][4][4];
#pragma unroll
    for (int mt = 0; mt < 2; mt++)
#pragma unroll
        for (int nt = 0; nt < 4; nt++)
#pragma unroll
            for (int e = 0; e < 4; e++) acc[mt][nt][e] = 0.0f;

    // channels-last slab: row (zs*6+ys)*34+xs, 32 channels, pitch 36 floats
    auto load_slab = [&](int cig) {
        for (int i = t; i < 4896; i += 256) {
            int zy = i / 272, r = i - zy * 272;
            int c4 = r / 34, xs = r - c4 * 34;
            int zs = zy / 6, ys = zy - zs * 6;
            int zg = z0 - 1 + zs, yg = y0 - 1 + ys, xg = xs - 1;
            bool ok = (unsigned)zg < 32u && (unsigned)yg < 32u && (unsigned)xg < 32u;
            int vox = zg * 1024 + yg * 32 + xg;
            float4 val;
            float* vp = &val.x;
            if (INMODE == 0) {
                // voxel mean straight from scatter sums (coalesced float4)
                float4 sums = ok ? __ldg((const float4*)(in + ((size_t)b * NV + vox) * CC
                                                          + cig * 32 + c4 * 4))
                                 : make_float4(0.f, 0.f, 0.f, 0.f);
                float inv = ok ? 1.0f / fmaxf(__ldg(cnt + (size_t)b * NV + vox), 1.0f) : 0.0f;
                val.x = tf32_rna(sums.x * inv);
                val.y = tf32_rna(sums.y * inv);
                val.z = tf32_rna(sums.z * inv);
                val.w = tf32_rna(sums.w * inv);
            } else {
                const float* inb = in + (size_t)b * CC * NV;
#pragma unroll
                for (int j = 0; j < 4; j++) {
                    int c = cig * 32 + c4 * 4 + j;
                    float v = ok ? __ldg(inb + (size_t)c * NV + vox) : 0.0f;
                    float u = fmaf(v, sc_sm[c], sh_sm[c]);
                    v = u >= 0 ? u : ALPHA * u;
                    if (!ok) v = 0.0f;
                    vp[j] = tf32_rna(v);
                }
            }
            *(float4*)(slab + (size_t)((zs * 6 + ys) * 34 + xs) * 36 + c4 * 4) = val;
        }
    };

    float4 wr0, wr1;
    auto w_prefetch = [&](int cig, int koff) {
        const float4* wg = (const float4*)(w + (size_t)(koff * 64 + cig * 32) * 64);
        wr0 = __ldg(&wg[t]);
        wr1 = __ldg(&wg[t + 256]);
    };
    auto w_sts = [&](float* dst) {
#pragma unroll
        for (int k = 0; k < 2; k++) {
            float4 v = k ? wr1 : wr0;
            int e = (t + k * 256) * 4;
            float* d = dst + (e >> 6) * 72 + (e & 63);
            d[0] = tf32_rna(v.x); d[1] = tf32_rna(v.y);
            d[2] = tf32_rna(v.z); d[3] = tf32_rna(v.w);
        }
    };

    auto compute = [&](int buf, int koff) {
        int dz = koff / 9, rem = koff - dz * 9;
        int dy = rem / 3, dx = rem - dy * 3;
        unsigned a_base = slab_s +
            (unsigned)((((dz * 6 + wy + dy) * 34) + gid + dx) * 36 + tig) * 4;
        unsigned b_base = wsm_s[buf] + (unsigned)(tig * 72 + wn * 32 + gid) * 4;
#pragma unroll
        for (int ks = 0; ks < 4; ks++) {
            unsigned ab = a_base + ks * 32;
            unsigned bb = b_base + ks * 2304;
            unsigned a0, a1, a2, a3, a4, a5, a6, a7;
            LDS32(a0, ab);            LDS32(a1, ab + 1152);
            LDS32(a2, ab + 16);       LDS32(a3, ab + 1168);
            LDS32(a4, ab + 2304);     LDS32(a5, ab + 3456);
            LDS32(a6, ab + 2320);     LDS32(a7, ab + 3472);
            unsigned b0[4], b1[4];
#pragma unroll
            for (int nt = 0; nt < 4; nt++) {
                LDS32(b0[nt], bb + nt * 32);
                LDS32(b1[nt], bb + nt * 32 + 1152);
            }
#pragma unroll
            for (int nt = 0; nt < 4; nt++) {
                MMA_TF32(acc[0][nt], a0, a1, a2, a3, b0[nt], b1[nt]);
                MMA_TF32(acc[1][nt], a4, a5, a6, a7, b0[nt], b1[nt]);
            }
        }
    };

#pragma unroll 1
    for (int cig = 0; cig < 2; cig++) {
        load_slab(cig);
        w_prefetch(cig, 0);
        w_sts(wsm0);
        __syncthreads();
#pragma unroll 1
        for (int koff = 0; koff < 27; koff++) {
            if (koff < 26) w_prefetch(cig, koff + 1);
            compute(koff & 1, koff);
            if (koff < 26) w_sts((koff & 1) ? wsm0 : wsm1);
            __syncthreads();
        }
    }

    // ---- epilogue: bounce D to smem, store + fused BN stats ----
#pragma unroll
    for (int mt = 0; mt < 2; mt++)
#pragma unroll
        for (int nt = 0; nt < 4; nt++) {
            int spat0 = wy * 32 + mt * 16 + gid;
            int cout0 = wn * 32 + nt * 8 + tig * 2;
            *(float2*)(res + spat0 * RES_PITCH + cout0) =
                make_float2(acc[mt][nt][0], acc[mt][nt][1]);
            *(float2*)(res + (spat0 + 8) * RES_PITCH + cout0) =
                make_float2(acc[mt][nt][2], acc[mt][nt][3]);
        }
    __syncthreads();

    if (OUTMODE == 0) {
        size_t obase = (size_t)b * CC * NV + (size_t)z0 * 1024 + (size_t)y0 * 32;
#pragma unroll
        for (int j = 0; j < 8; j++) {
            int c = wid * 8 + j;
            float bval = bias_sm[c];
            float s = 0, q = 0;
#pragma unroll
            for (int sy = 0; sy < 4; sy++) {
                float v = res[(sy * 32 + lane) * RES_PITCH + c] + bval;
                out[obase + (size_t)c * NV + sy * 32 + lane] = v;
                s += v; q += v * v;
            }
#pragma unroll
            for (int o = 16; o > 0; o >>= 1) {
                s += __shfl_xor_sync(0xffffffff, s, o);
                q += __shfl_xor_sync(0xffffffff, q, o);
            }
            if (lane == 0) { atomicAdd(&gsum[c], s); atomicAdd(&gsumsq[c], q); }
        }
    } else {
        // channels-last store: thread t -> spat s = t>>1, half h = t&1
        int s_ = t >> 1, h = t & 1;
        int vox = z0 * 1024 + (y0 + (s_ >> 5)) * 32 + (s_ & 31);
        float* op = out + ((size_t)b * NV + vox) * CC + h * 32;
        const float* rp = res + s_ * RES_PITCH + h * 32;
#pragma unroll
        for (int k = 0; k < 8; k++) {
            float4 v;
            v.x = rp[4 * k + 0] + bias_sm[h * 32 + 4 * k + 0];
            v.y = rp[4 * k + 1] + bias_sm[h * 32 + 4 * k + 1];
            v.z = rp[4 * k + 2] + bias_sm[h * 32 + 4 * k + 2];
            v.w = rp[4 * k + 3] + bias_sm[h * 32 + 4 * k + 3];
            *(float4*)(op + 4 * k) = v;
        }
        // stats pass (same as channel-major)
#pragma unroll
        for (int j = 0; j < 8; j++) {
            int c = wid * 8 + j;
            float bval = bias_sm[c];
            float s = 0, q = 0;
#pragma unroll
            for (int sy = 0; sy < 4; sy++) {
                float v = res[(sy * 32 + lane) * RES_PITCH + c] + bval;
                s += v; q += v * v;
            }
#pragma unroll
            for (int o = 16; o > 0; o >>= 1) {
                s += __shfl_xor_sync(0xffffffff, s, o);
                q += __shfl_xor_sync(0xffffffff, q, o);
            }
            if (lane == 0) { atomicAdd(&gsum[c], s); atomicAdd(&gsumsq[c], q); }
        }
    }
}

// ================= tf32 mma.sync point GEMM + fused stats ===================
// CTA: 128 points x 64 cout, K=64 (2 cig x 4 K8-steps). A from fT [b][n][c],
// staged pitch-36 per cig (same fragment map as conv). B = W, pitch 72.
// Output pT [b][n][c] channels-last. Stats fused.
#define PG_A_FLOATS (2 * 128 * 36)    // 9216
#define PG_DYN ((PG_A_FLOATS + 2 * WSM_FLOATS) * 4)   // 55296 B

__global__ __launch_bounds__(256, 2)
void pgemm_mma(const float* __restrict__ fT, const float* __restrict__ w,
               const float* __restrict__ bias, float* __restrict__ pT,
               float* __restrict__ gsum, float* __restrict__ gsumsq) {
    extern __shared__ __align__(16) float dsm[];
    __shared__ float bias_sm[64];
    float* asm0 = dsm;                       // [cig][128][36]
    float* wsm0 = dsm + PG_A_FLOATS;         // [cig][32][72]
    float* res = dsm;                        // reuse after compute

    int b = blockIdx.y;
    int n0 = blockIdx.x * 128;
    int t = threadIdx.x, lane = t & 31, wid = t >> 5;
    int wy = wid >> 1, wn = wid & 1;
    int gid = lane >> 2, tig = lane & 3;

    unsigned a_s = (unsigned)__cvta_generic_to_shared(asm0);
    unsigned w_s = (unsigned)__cvta_generic_to_shared(wsm0);

    if (t < 64) bias_sm[t] = bias[t];

    // stage A: fT rows n0..n0+127, 64 ch -> [cig][n][36]
    for (int i = t; i < 2048; i += 256) {          // 128 n x 16 c4
        int n = i >> 4, c4 = i & 15;
        int cig = c4 >> 3, c4l = c4 & 7;
        float4 v = __ldg((const float4*)(fT + ((size_t)b * NP + n0 + n) * CC + c4 * 4));
        v.x = tf32_rna(v.x); v.y = tf32_rna(v.y);
        v.z = tf32_rna(v.z); v.w = tf32_rna(v.w);
        *(float4*)(asm0 + (size_t)cig * 128 * 36 + n * 36 + c4l * 4) = v;
    }
    // stage W: [cig][ci 32][72]
    {
        const float4* wg = (const float4*)w;
#pragma unroll
        for (int k = 0; k < 4; k++) {
            float4 v = __ldg(&wg[t + k * 256]);
            int e = (t + k * 256) * 4;              // index in [ci*64+co]
            int ci = e >> 6, co = e & 63;
            float* d = wsm0 + (size_t)(ci >> 5) * WSM_FLOATS + (ci & 31) * 72 + co;
            d[0] = tf32_rna(v.x); d[1] = tf32_rna(v.y);
            d[2] = tf32_rna(v.z); d[3] = tf32_rna(v.w);
        }
    }
    __syncthreads();

    float acc[2][4][4];
#pragma unroll
    for (int mt = 0; mt < 2; mt++)
#pragma unroll
        for (int nt = 0; nt < 4; nt++)
#pragma unroll
            for (int e = 0; e < 4; e++) acc[mt][nt][e] = 0.0f;

#pragma unroll
    for (int cig = 0; cig < 2; cig++) {
        unsigned a_base = a_s + (unsigned)(cig * 128 * 36 + (wy * 32 + gid) * 36 + tig) * 4;
        unsigned b_base = w_s + (unsigned)(cig * WSM_FLOATS + tig * 72 + wn * 32 + gid) * 4;
#pragma unroll
        for (int ks = 0; ks < 4; ks++) {
            unsigned ab = a_base + ks * 32;
            unsigned bb = b_base + ks * 2304;
            unsigned a0, a1, a2, a3, a4, a5, a6, a7;
            LDS32(a0, ab);            LDS32(a1, ab + 1152);
            LDS32(a2, ab + 16);       LDS32(a3, ab + 1168);
            LDS32(a4, ab + 2304);     LDS32(a5, ab + 3456);
            LDS32(a6, ab + 2320);     LDS32(a7, ab + 3472);
            unsigned b0[4], b1[4];
#pragma unroll
            for (int nt = 0; nt < 4; nt++) {
                LDS32(b0[nt], bb + nt * 32);
                LDS32(b1[nt], bb + nt * 32 + 1152);
            }
#pragma unroll
            for (int nt = 0; nt < 4; nt++) {
                MMA_TF32(acc[0][nt], a0, a1, a2, a3, b0[nt], b1[nt]);
                MMA_TF32(acc[1][nt], a4, a5, a6, a7, b0[nt], b1[nt]);
            }
        }
    }
    __syncthreads();   // done reading A/W smem; res aliases it

#pragma unroll
    for (int mt = 0; mt < 2; mt++)
#pragma unroll
        for (int nt = 0; nt < 4; nt++) {
            int spat0 = wy * 32 + mt * 16 + gid;
            int cout0 = wn * 32 + nt * 8 + tig * 2;
            *(float2*)(res + spat0 * RES_PITCH + cout0) =
                make_float2(acc[mt][nt][0], acc[mt][nt][1]);
            *(float2*)(res + (spat0 + 8) * RES_PITCH + cout0) =
                make_float2(acc[mt][nt][2], acc[mt][nt][3]);
        }
    __syncthreads();

    // channels-last store into pT + fused stats
    {
        int s_ = t >> 1, h = t & 1;
        float* op = pT + ((size_t)b * NP + n0 + s_) * CC + h * 32;
        const float* rp = res + s_ * RES_PITCH + h * 32;
#pragma unroll
        for (int k = 0; k < 8; k++) {
            float4 v;
            v.x = rp[4 * k + 0] + bias_sm[h * 32 + 4 * k + 0];
            v.y = rp[4 * k + 1] + bias_sm[h * 32 + 4 * k + 1];
            v.z = rp[4 * k + 2] + bias_sm[h * 32 + 4 * k + 2];
            v.w = rp[4 * k + 3] + bias_sm[h * 32 + 4 * k + 3];
            *(float4*)(op + 4 * k) = v;
        }
    }
#pragma unroll
    for (int j = 0; j < 8; j++) {
        int c = wid * 8 + j;
        float bval = bias_sm[c];
        float s = 0, q = 0;
#pragma unroll
        for (int sy = 0; sy < 4; sy++) {
            float v = res[(sy * 32 + lane) * RES_PITCH + c] + bval;
            s += v; q += v * v;
        }
#pragma unroll
        for (int o = 16; o > 0; o >>= 1) {
            s += __shfl_xor_sync(0xffffffff, s, o);
            q += __shfl_xor_sync(0xffffffff, q, o);
        }
        if (lane == 0) { atomicAdd(&gsum[c], s); atomicAdd(&gsumsq[c], q); }
    }
}

// ---------------- final: devox(BN2+lrelu on the fly) + BN(p)+lrelu + add ----
__global__ void final_k(const float* __restrict__ vT, const float* __restrict__ pT,
                        const float* __restrict__ normc,
                        const float* __restrict__ sc2, const float* __restrict__ sh2,
                        const float* __restrict__ scp, const float* __restrict__ shp,
                        float* __restrict__ out) {
    __shared__ float res[64][65];
    __shared__ int cidx[64][8];
    __shared__ float cw[64][8];
    int b = blockIdx.y;
    int n0 = blockIdx.x * 64;
    int t = threadIdx.x;

    if (t < 64) {
        int n = n0 + t;
        float xs = normc[(b * 3 + 0) * NP + n];
        float ys = normc[(b * 3 + 1) * NP + n];
        float zs = normc[(b * 3 + 2) * NP + n];
        float x0f = floorf(xs), y0f = floorf(ys), z0f = floorf(zs);
        float fx = xs - x0f, fy = ys - y0f, fz = zs - z0f;
        int x0 = (int)x0f, y0 = (int)y0f, z0 = (int)z0f;
        int x1 = min(x0 + 1, 31), y1 = min(y0 + 1, 31), z1 = min(z0 + 1, 31);
#pragma unroll
        for (int k = 0; k < 8; k++) {
            int dx = (k >> 2) & 1, dy = (k >> 1) & 1, dz = k & 1;
            float wt = (dx ? fx : 1.0f - fx) * (dy ? fy : 1.0f - fy) * (dz ? fz : 1.0f - fz);
            int idx = ((dx ? x1 : x0) * 32 + (dy ? y1 : y0)) * 32 + (dz ? z1 : z0);
            cidx[t][k] = idx;
            cw[t][k] = wt;
        }
    }
    __syncthreads();

    int c = t & 63, ty = t >> 6;
    float sc2v = sc2[c], sh2v = sh2[c];
    float scpv = scp[c], shpv = shp[c];

    for (int j = ty; j < 64; j += 4) {
        float acc = 0.0f;
#pragma unroll
        for (int k = 0; k < 8; k++) {
            float g = vT[((size_t)b * NV + cidx[j][k]) * CC + c];
            float u = fmaf(g, sc2v, sh2v);
            u = u >= 0 ? u : ALPHA * u;
            acc += cw[j][k] * u;
        }
        float pv = fmaf(pT[((size_t)b * NP + n0 + j) * CC + c], scpv, shpv);
        pv = pv >= 0 ? pv : ALPHA * pv;
        res[c][j] = acc + pv;
    }
    __syncthreads();

    for (int i = t; i < 4096; i += 256) {
        int c2 = i >> 6, j = i & 63;
        out[((size_t)b * CC + c2) * NP + n0 + j] = res[c2][j];
    }
}

// ---------------- launcher ----------------
extern "C" void kernel_launch(void* const* d_in, const int* in_sizes, int n_in,
                              void* d_out, int out_size) {
    const float* feat   = (const float*)d_in[0];
    const float* coords = (const float*)d_in[1];
    const float* c1w    = (const float*)d_in[2];
    const float* c1b    = (const float*)d_in[3];
    const float* g1     = (const float*)d_in[4];
    const float* b1     = (const float*)d_in[5];
    const float* c2w    = (const float*)d_in[6];
    const float* c2b    = (const float*)d_in[7];
    const float* g2     = (const float*)d_in[8];
    const float* b2     = (const float*)d_in[9];
    const float* pw     = (const float*)d_in[10];
    const float* pb     = (const float*)d_in[11];
    const float* pg     = (const float*)d_in[12];
    const float* pbeta  = (const float*)d_in[13];
    float* out = (float*)d_out;

    float *fT, *tmp, *cnt, *bufB, *pT, *normc, *cmean, *stats, *scsh;
    unsigned* cmaxb;
    cudaGetSymbolAddress((void**)&fT, g_fT);
    cudaGetSymbolAddress((void**)&tmp, g_tmp);
    cudaGetSymbolAddress((void**)&cnt, g_cnt);
    cudaGetSymbolAddress((void**)&bufB, g_bufB);
    cudaGetSymbolAddress((void**)&pT, g_pT);
    cudaGetSymbolAddress((void**)&normc, g_normc);
    cudaGetSymbolAddress((void**)&cmean, g_cmean);
    cudaGetSymbolAddress((void**)&cmaxb, g_cmaxb);
    cudaGetSymbolAddress((void**)&stats, g_stats);
    cudaGetSymbolAddress((void**)&scsh, g_scsh);

    float* sum1 = stats + 0 * CC;  float* sq1 = stats + 1 * CC;
    float* sum2 = stats + 2 * CC;  float* sq2 = stats + 3 * CC;
    float* psum = stats + 4 * CC;  float* psq = stats + 5 * CC;
    float* sc1 = scsh + 0 * CC;    float* sh1 = scsh + 1 * CC;
    float* sc2 = scsh + 2 * CC;    float* sh2 = scsh + 3 * CC;
    float* scp = scsh + 4 * CC;    float* shp = scsh + 5 * CC;

    cudaFuncSetAttribute(conv3d_mma<0, 0>, cudaFuncAttributeMaxDynamicSharedMemorySize, CONV_DYN);
    cudaFuncSetAttribute(conv3d_mma<1, 1>, cudaFuncAttributeMaxDynamicSharedMemorySize, CONV_DYN);
    cudaFuncSetAttribute(pgemm_mma, cudaFuncAttributeMaxDynamicSharedMemorySize, PG_DYN);

    const float invV = 1.0f / (float)(BB * NV);
    const float invP = 1.0f / (float)(BB * NP);

    // voxelize
    zero_kernel<<<8192, 256>>>(tmp, (size_t)BB * NV * CC);
    zero_kernel<<<256, 256>>>(cnt, (size_t)BB * NV);
    zero_small<<<1, 512>>>(stats, cmean, cmaxb);
    transpose_feat<<<dim3(NP / 32, BB), 256>>>(feat, fT);
    coord_mean_p<<<dim3(32, BB), 256>>>(coords, cmean);
    coord_max_p<<<dim3(32, BB), 256>>>(coords, cmean, cmaxb);
    scatter<<<BB * NP / 4, 256>>>(coords, fT, cmean, cmaxb, normc, tmp, cnt);

    // conv1: reads voxel sums+counts directly (finalize fused), out channel-major
    conv3d_mma<0, 0><<<dim3(8, 32, BB), 256, CONV_DYN>>>(tmp, cnt, bufB, c1w, c1b,
                                                         nullptr, nullptr, sum1, sq1);
    mkscale<<<1, 64>>>(sum1, sq1, g1, b1, invV, sc1, sh1);

    // conv2: BN1+lrelu fused at load, channels-last out into tmp (raw conv+bias)
    conv3d_mma<1, 1><<<dim3(8, 32, BB), 256, CONV_DYN>>>(bufB, nullptr, tmp, c2w, c2b,
                                                         sc1, sh1, sum2, sq2);
    mkscale<<<1, 64>>>(sum2, sq2, g2, b2, invV, sc2, sh2);

    // point branch: tensor-core GEMM + fused stats
    pgemm_mma<<<dim3(NP / 128, BB), 256, PG_DYN>>>(fT, pw, pb, pT, psum, psq);
    mkscale<<<1, 64>>>(psum, psq, pg, pbeta, invP, scp, shp);

    // devoxelize (BN2+lrelu applied on gather) + point BN + add
    final_k<<<dim3(NP / 64, BB), 256>>>(tmp, pT, normc, sc2, sh2, scp, shp, out);

    // coords passthrough (second tuple output), if the harness expects it
    int main_sz = BB * CC * NP;
    int coord_sz = BB * 3 * NP;
    if (out_size >= main_sz + coord_sz)
        copy_kernel<<<coord_sz / 256, 256>>>(coords, out + main_sz, coord_sz);
}